// round 11
// baseline (speedup 1.0000x reference)
#include <cuda_runtime.h>
#include <cuda_bf16.h>
#include <math.h>
#include <stdint.h>

#define NSUP 16384
#define NQ   8192
#define DIM  256
#define NCLS 64
#define SBIN 2048
#define SKRANK 1048576ULL   /* (1024*2048)/2 */
#define NT   8192           /* d2 tiles: 64 x 128 */

__device__ float g_psum[NCLS*DIM];
__device__ float g_cnt[NCLS];
__device__ float g_protoT[DIM*NCLS];
__device__ float g_musum[DIM];
__device__ float g_mu[DIM];
__device__ float g_G[DIM*DIM];
__device__ float g_Y[DIM*DIM];
__device__ float g_Z[DIM*DIM];
__device__ float g_T[DIM*DIM];
__device__ float g_Y2[DIM*DIM];
__device__ float g_Z2[DIM*DIM];
__device__ float g_trsum;
__device__ float g_gamma;
__device__ __nv_bfloat16 g_shi[NSUP*DIM];
__device__ __nv_bfloat16 g_qhi[NQ*DIM];
__device__ float g_sn[NSUP];
__device__ float g_qn[NQ];
__device__ float g_accw[NQ];
__device__ float g_accwv[NQ];
__device__ unsigned int g_h1[SBIN];

__device__ __forceinline__ float warp_sum(float v){
    #pragma unroll
    for (int o = 16; o; o >>= 1) v += __shfl_xor_sync(0xffffffffu, v, o);
    return v;
}
__device__ __forceinline__ float warp_max(float v){
    #pragma unroll
    for (int o = 16; o; o >>= 1) v = fmaxf(v, __shfl_xor_sync(0xffffffffu, v, o));
    return v;
}
__device__ __forceinline__ float* bsel(int id){
    switch(id){ case 0: return g_Y; case 1: return g_Z; case 2: return g_T;
                case 3: return g_Y2; default: return g_Z2; }
}
__device__ __forceinline__ uint32_t smem_u32(const void* p){
    uint32_t a;
    asm("{ .reg .u64 t; cvta.to.shared.u64 t, %1; cvt.u32.u64 %0, t; }" : "=r"(a) : "l"(p));
    return a;
}
__device__ __forceinline__ void cp16(uint32_t saddr, const void* gptr){
    asm volatile("cp.async.cg.shared.global [%0], [%1], 16;" :: "r"(saddr), "l"(gptr));
}
#define CP_COMMIT() asm volatile("cp.async.commit_group;" ::: "memory")
#define CP_WAIT(n)  asm volatile("cp.async.wait_group %0;" :: "n"(n) : "memory")
#define LDSM4(r0,r1,r2,r3,addr) \
    asm volatile("ldmatrix.sync.aligned.m8n8.x4.shared.b16 {%0,%1,%2,%3}, [%4];" \
        : "=r"(r0),"=r"(r1),"=r"(r2),"=r"(r3) : "r"(addr))
#define MMA16816(c,a,b) \
    asm volatile("mma.sync.aligned.m16n8k16.row.col.f32.bf16.bf16.f32 " \
        "{%0,%1,%2,%3},{%4,%5,%6,%7},{%8,%9},{%0,%1,%2,%3};" \
        : "+f"((c)[0]),"+f"((c)[1]),"+f"((c)[2]),"+f"((c)[3]) \
        : "r"((a)[0]),"r"((a)[1]),"r"((a)[2]),"r"((a)[3]), "r"((b)[0]),"r"((b)[1]))

// ---------------------------------------------------------------------------
extern "C" __global__ void k_zero(){
    int i = blockIdx.x*blockDim.x + threadIdx.x, st = gridDim.x*blockDim.x;
    for (int e=i; e<NCLS*DIM; e+=st) g_psum[e]=0.f;
    for (int e=i; e<NCLS;     e+=st) g_cnt[e]=0.f;
    for (int e=i; e<DIM;      e+=st) g_musum[e]=0.f;
    for (int e=i; e<DIM*DIM;  e+=st) g_G[e]=0.f;
    for (int e=i; e<SBIN;     e+=st) g_h1[e]=0u;
    for (int e=i; e<NSUP;     e+=st) g_sn[e]=0.f;
    for (int e=i; e<NQ;       e+=st){ g_qn[e]=0.f; g_accw[e]=0.f; g_accwv[e]=0.f; }
    if (i==0) g_trsum = 0.f;
}

// smem class-sum accumulation (64 blocks x 256 rows)
#define SUP_SM ((NCLS*DIM + NCLS)*4)
extern "C" __global__ __launch_bounds__(256) void k_support(
        const float* __restrict__ sf, const int* __restrict__ lab){
    extern __shared__ float sp[];            // [NCLS*DIM] + [NCLS]
    float* sc = sp + NCLS*DIM;
    int tid = threadIdx.x, w = tid>>5, lane = tid&31;
    for (int i=tid; i<NCLS*DIM; i+=256) sp[i]=0.f;
    if (tid < NCLS) sc[tid]=0.f;
    __syncthreads();
    int r0 = blockIdx.x * (NSUP/64);
    float msum[8];
    #pragma unroll
    for (int t=0;t<8;t++) msum[t]=0.f;
    for (int r = r0+w; r < r0 + NSUP/64; r += 8){
        const float* row = sf + (size_t)r*DIM;
        float x[8], ss=0.f;
        #pragma unroll
        for (int t=0;t<8;t++){ x[t]=row[lane+32*t]; ss += x[t]*x[t]; }
        ss = warp_sum(ss);
        float inv = 1.f / fmaxf(sqrtf(ss), 1e-8f);
        int lb = lab[r];
        #pragma unroll
        for (int t=0;t<8;t++){
            msum[t] += x[t];
            atomicAdd(&sp[lb*DIM + lane + 32*t], x[t]*inv);
        }
        if (!lane) atomicAdd(&sc[lb], 1.f);
    }
    #pragma unroll
    for (int t=0;t<8;t++) atomicAdd(&g_musum[lane+32*t], msum[t]);
    __syncthreads();
    for (int i=tid; i<NCLS*DIM; i+=256){
        float v = sp[i];
        if (v != 0.f) atomicAdd(&g_psum[i], v);
    }
    if (tid < NCLS && sc[tid] != 0.f) atomicAdd(&g_cnt[tid], sc[tid]);
}

// block 0: mu; blocks 1..8: 8 classes each (warp per class)
extern "C" __global__ void k_finalize(){
    int tid = threadIdx.x, w = tid>>5, lane = tid&31;
    if (blockIdx.x == 0){
        if (tid < DIM) g_mu[tid] = g_musum[tid] * (1.f/NSUP);
        return;
    }
    int c = (blockIdx.x-1)*8 + w;
    float ic = 1.f / fmaxf(g_cnt[c], 1.f);
    float v[8], ss=0.f;
    #pragma unroll
    for (int t=0;t<8;t++){ v[t]=g_psum[c*DIM+lane+32*t]*ic; ss+=v[t]*v[t]; }
    ss = warp_sum(ss);
    float inv = 1.f / fmaxf(sqrtf(ss), 1e-8f);
    #pragma unroll
    for (int t=0;t<8;t++) g_protoT[(lane+32*t)*NCLS + c] = v[t]*inv;
}

extern "C" __global__ __launch_bounds__(256) void k_logits(
        const float* __restrict__ qf, float* __restrict__ out){
    __shared__ float sq[4][260];
    __shared__ float sred[8], sinv[4], smax[8], ssum[8];
    int tid = threadIdx.x, w = tid>>5, lane = tid&31;
    int q0 = blockIdx.x*4;
    #pragma unroll
    for (int p=0;p<4;p++) sq[p][tid] = qf[(size_t)(q0+p)*DIM + tid];
    __syncthreads();
    { int row = w>>1, base = (w&1)*128;
      float s=0.f;
      #pragma unroll
      for (int t=0;t<4;t++){ float v=sq[row][base+lane+32*t]; s+=v*v; }
      s = warp_sum(s);
      if (!lane) sred[w]=s; }
    __syncthreads();
    if (tid<4) sinv[tid] = 1.f / fmaxf(sqrtf(sred[2*tid]+sred[2*tid+1]), 1e-8f);
    __syncthreads();
    int c = tid&63, qi = tid>>6;
    float acc = 0.f;
    #pragma unroll 8
    for (int k=0;k<DIM;k++) acc = fmaf(sq[qi][k], g_protoT[k*NCLS+c], acc);
    acc *= sinv[qi];
    float m = warp_max(acc);
    if (!lane) smax[w]=m;
    __syncthreads();
    m = fmaxf(smax[qi*2], smax[qi*2+1]);
    float e = expf(acc - m);
    float s = warp_sum(e);
    if (!lane) ssum[w]=s;
    __syncthreads();
    float lse = m + logf(ssum[qi*2]+ssum[qi*2+1]);
    out[(size_t)(q0+qi)*NCLS + c] = acc - lse;
}

extern "C" __global__ __launch_bounds__(256) void k_covgemm(const float* __restrict__ X){
    __shared__ float Xa[16][68], Xb[16][68];
    int tid = threadIdx.x, tx = tid&15, ty = tid>>4;
    int i0 = blockIdx.y*64, j0 = blockIdx.x*64;
    int chunk = NSUP/gridDim.z, rb = blockIdx.z*chunk;
    float acc[4][4] = {};
    for (int r = rb; r < rb+chunk; r += 16){
        #pragma unroll
        for (int p=0;p<4;p++){
            int lin = tid + p*256, rr = lin>>6, c = lin&63;
            Xa[rr][c] = X[(size_t)(r+rr)*DIM + i0 + c];
            Xb[rr][c] = X[(size_t)(r+rr)*DIM + j0 + c];
        }
        __syncthreads();
        #pragma unroll
        for (int kk=0;kk<16;kk++){
            float a[4], b[4];
            #pragma unroll
            for (int u=0;u<4;u++){ a[u]=Xa[kk][ty*4+u]; b[u]=Xb[kk][tx*4+u]; }
            #pragma unroll
            for (int u=0;u<4;u++)
                #pragma unroll
                for (int v=0;v<4;v++) acc[u][v]=fmaf(a[u],b[v],acc[u][v]);
        }
        __syncthreads();
    }
    #pragma unroll
    for (int u=0;u<4;u++)
        #pragma unroll
        for (int v=0;v<4;v++)
            atomicAdd(&g_G[(i0+ty*4+u)*DIM + j0+tx*4+v], acc[u][v]);
}

extern "C" __global__ void k_covA(){
    __shared__ float red[256];
    int tid = threadIdx.x;
    float tr = 0.f;
    #pragma unroll
    for (int p=0;p<4;p++){
        int e = blockIdx.x*1024 + p*256 + tid;
        int i = e>>8, j = e&255;
        float v = (g_G[e] - (float)NSUP*g_mu[i]*g_mu[j]) * (1.f/(NSUP-1));
        if (i==j){ v += 1e-4f; tr += v; }
        g_T[e] = v;
    }
    red[tid]=tr; __syncthreads();
    for (int s=128;s;s>>=1){ if(tid<s) red[tid]+=red[tid+s]; __syncthreads(); }
    if (!tid && red[0] != 0.f) atomicAdd(&g_trsum, red[0]);
}

extern "C" __global__ void k_covB(){
    float ic = (float)DIM / g_trsum;
    int tid = threadIdx.x;
    #pragma unroll
    for (int p=0;p<4;p++){
        int e = blockIdx.x*1024 + p*256 + tid;
        int i = e>>8, j = e&255;
        g_Y[e] = g_T[e]*ic;
        g_Z[e] = (i==j)?1.f:0.f;
    }
}

extern "C" __global__ __launch_bounds__(256) void k_mm256(int ia,int ib,int ic,int mode){
    const float* A = bsel(ia); const float* B = bsel(ib); float* C = bsel(ic);
    __shared__ float As[32][33], Bs[32][33];
    int tid = threadIdx.x, tx = tid&15, ty = tid>>4;
    int j0 = blockIdx.x*32, i0 = blockIdx.y*32;
    float a00=0,a01=0,a10=0,a11=0;
    for (int k0=0;k0<DIM;k0+=32){
        #pragma unroll
        for (int p=0;p<4;p++){
            int lin = tid+p*256, r = lin>>5, c = lin&31;
            As[r][c] = A[(i0+r)*DIM + k0+c];
            Bs[r][c] = B[(k0+r)*DIM + j0+c];
        }
        __syncthreads();
        #pragma unroll
        for (int kk=0;kk<32;kk++){
            float x0=As[ty*2][kk], x1=As[ty*2+1][kk];
            float y0=Bs[kk][tx*2], y1=Bs[kk][tx*2+1];
            a00=fmaf(x0,y0,a00); a01=fmaf(x0,y1,a01);
            a10=fmaf(x1,y0,a10); a11=fmaf(x1,y1,a11);
        }
        __syncthreads();
    }
    int i = i0+ty*2, j = j0+tx*2;
    float o[2][2] = {{a00,a01},{a10,a11}};
    #pragma unroll
    for (int u=0;u<2;u++)
        #pragma unroll
        for (int v=0;v<2;v++){
            float val = o[u][v];
            if (mode==0) val = ((i+u==j+v)?1.5f:0.f) - 0.5f*val;
            C[(i+u)*DIM + j+v] = val;
        }
}

extern "C" __global__ __launch_bounds__(256) void k_mm256pair(int py,int pz,int py2,int pz2){
    const float* A; const float* B; float* C;
    if (blockIdx.z == 0){ A = bsel(py); B = g_T; C = bsel(py2); }
    else                { A = g_T; B = bsel(pz); C = bsel(pz2); }
    __shared__ float As[32][33], Bs[32][33];
    int tid = threadIdx.x, tx = tid&15, ty = tid>>4;
    int j0 = blockIdx.x*32, i0 = blockIdx.y*32;
    float a00=0,a01=0,a10=0,a11=0;
    for (int k0=0;k0<DIM;k0+=32){
        #pragma unroll
        for (int p=0;p<4;p++){
            int lin = tid+p*256, r = lin>>5, c = lin&31;
            As[r][c] = A[(i0+r)*DIM + k0+c];
            Bs[r][c] = B[(k0+r)*DIM + j0+c];
        }
        __syncthreads();
        #pragma unroll
        for (int kk=0;kk<32;kk++){
            float x0=As[ty*2][kk], x1=As[ty*2+1][kk];
            float y0=Bs[kk][tx*2], y1=Bs[kk][tx*2+1];
            a00=fmaf(x0,y0,a00); a01=fmaf(x0,y1,a01);
            a10=fmaf(x1,y0,a10); a11=fmaf(x1,y1,a11);
        }
        __syncthreads();
    }
    int i = i0+ty*2, j = j0+tx*2;
    C[i*DIM + j]       = a00;
    C[i*DIM + j+1]     = a01;
    C[(i+1)*DIM + j]   = a10;
    C[(i+1)*DIM + j+1] = a11;
}

// whiten + fused muZ + fused bf16 convert + fused row-norm partials
extern "C" __global__ __launch_bounds__(256) void k_whiten(
        const float* __restrict__ Xin, int zid, int wsel){
    const float* M = bsel(zid);
    __nv_bfloat16* Bout = wsel ? g_qhi : g_shi;
    float* Nout = wsel ? g_qn : g_sn;
    __shared__ float Xs[16][132], Ms[16][68];
    __shared__ float muzp[4][64];
    __shared__ float muz[64];
    int tid = threadIdx.x, tx = tid&15, ty = tid>>4;
    int m0 = blockIdx.y*128, j0 = blockIdx.x*64;
    { int col = tid>>2, part = tid&3;
      float s = 0.f;
      #pragma unroll 16
      for (int k=part*64; k<part*64+64; k++) s = fmaf(g_mu[k], M[k*DIM + j0 + col], s);
      muzp[part][col] = s; }
    __syncthreads();
    if (tid < 64) muz[tid] = muzp[0][tid]+muzp[1][tid]+muzp[2][tid]+muzp[3][tid];
    float acc[8][4] = {};
    for (int k0=0;k0<DIM;k0+=16){
        #pragma unroll
        for (int p=0;p<2;p++){
            int lin = tid+p*256, m = lin>>2, c4 = (lin&3)*4;
            float4 v = *(const float4*)(Xin + (size_t)(m0+m)*DIM + k0 + c4);
            Xs[c4][m]=v.x; Xs[c4+1][m]=v.y; Xs[c4+2][m]=v.z; Xs[c4+3][m]=v.w;
        }
        { int r = tid>>4, c4 = (tid&15)*4;
          *(float4*)&Ms[r][c4] = *(const float4*)(M + (k0+r)*DIM + j0 + c4); }
        __syncthreads();
        #pragma unroll
        for (int kk=0;kk<16;kk++){
            float av[8], bv[4];
            #pragma unroll
            for (int u=0;u<8;u++) av[u]=Xs[kk][ty*8+u];
            #pragma unroll
            for (int v=0;v<4;v++) bv[v]=Ms[kk][tx*4+v];
            #pragma unroll
            for (int u=0;u<8;u++)
                #pragma unroll
                for (int v=0;v<4;v++) acc[u][v]=fmaf(av[u],bv[v],acc[u][v]);
        }
        __syncthreads();
    }
    float rs = sqrtf((float)DIM / g_trsum);
    float mz[4];
    #pragma unroll
    for (int v=0;v<4;v++) mz[v] = muz[tx*4+v];
    #pragma unroll
    for (int u=0;u<8;u++){
        float vv[4]; float ss = 0.f;
        #pragma unroll
        for (int v=0;v<4;v++){ vv[v]=(acc[u][v]-mz[v])*rs; ss += vv[v]*vv[v]; }
        __nv_bfloat16 h[4];
        #pragma unroll
        for (int v=0;v<4;v++) h[v] = __float2bfloat16_rn(vv[v]);
        int row = m0 + ty*8 + u;
        *(ushort4*)(Bout + (size_t)row*DIM + j0 + tx*4) =
            make_ushort4(*(unsigned short*)&h[0], *(unsigned short*)&h[1],
                         *(unsigned short*)&h[2], *(unsigned short*)&h[3]);
        atomicAdd(&Nout[row], ss);
    }
}

// ---- sample d2 GEMM for gamma ---------------------------------------------
#define SMA   0
#define SMB   16384
#define SMX_S 32768
#define SMT_S 40960
#define SMX_M 65536
#define SMT_M 67072

extern "C" __global__ __launch_bounds__(256) void k_d2samp(){
    extern __shared__ char smem[];
    uint32_t sb = smem_u32(smem);
    unsigned int* sh = (unsigned int*)(smem + SMX_S);
    int tid = threadIdx.x, wid = tid>>5, lane = tid&31;
    int m0 = blockIdx.y*128, n0 = blockIdx.x*128;
    int wm0 = (wid&1)*64, wn0 = (wid>>1)*32;
    for (int b=tid;b<SBIN;b+=256) sh[b]=0u;
    float acc[4][4][4] = {};
    int g = lane>>3, lr = lane&7;
    for (int kc=0;kc<4;kc++){
        #pragma unroll
        for (int p=0;p<4;p++){
            int idx = tid + p*256;
            int r = idx>>3, c = idx&7;
            size_t go = (size_t)r*DIM + kc*64 + c*8;
            uint32_t so = (uint32_t)(r*128 + ((c ^ (r&7))<<4));
            *(uint4*)(smem+SMA+so) = *(const uint4*)(g_qhi + (size_t)m0*DIM + go);
            *(uint4*)(smem+SMB+so) = *(const uint4*)(g_shi + (size_t)n0*DIM + go);
        }
        __syncthreads();
        #pragma unroll
        for (int s=0;s<4;s++){
            int cc = s*2 + (g>>1);
            uint32_t a[4][4], bfr[4][2];
            #pragma unroll
            for (int mf=0;mf<4;mf++){
                int r = wm0 + mf*16 + (g&1)*8 + lr;
                LDSM4(a[mf][0],a[mf][1],a[mf][2],a[mf][3], sb + SMA + r*128 + ((cc ^ (r&7))<<4));
            }
            #pragma unroll
            for (int np=0;np<2;np++){
                int r = wn0 + np*16 + (g&1)*8 + lr;
                uint32_t t0,t1,t2,t3;
                LDSM4(t0,t1,t2,t3, sb + SMB + r*128 + ((cc ^ (r&7))<<4));
                bfr[np*2][0]=t0;   bfr[np*2][1]=t2;
                bfr[np*2+1][0]=t1; bfr[np*2+1][1]=t3;
            }
            #pragma unroll
            for (int mf=0;mf<4;mf++)
                #pragma unroll
                for (int nf=0;nf<4;nf++)
                    MMA16816(acc[mf][nf], a[mf], bfr[nf]);
        }
        __syncthreads();
    }
    int rbase = m0 + wm0 + (lane>>2);
    int cbase = n0 + wn0 + (lane&3)*2;
    #pragma unroll
    for (int mf=0;mf<4;mf++)
        #pragma unroll
        for (int h=0;h<2;h++){
            float qn = g_qn[rbase + mf*16 + h*8];
            #pragma unroll
            for (int nf=0;nf<4;nf++){
                int col = cbase + nf*8;
                float v0 = fmaxf(qn + g_sn[col]   - 2.f*acc[mf][nf][h*2+0], 0.f);
                float v1 = fmaxf(qn + g_sn[col+1] - 2.f*acc[mf][nf][h*2+1], 0.f);
                int b0=(int)(v0*2.0f); if(b0>SBIN-1)b0=SBIN-1;
                int b1=(int)(v1*2.0f); if(b1>SBIN-1)b1=SBIN-1;
                atomicAdd(&sh[b0],1u); atomicAdd(&sh[b1],1u);
            }
        }
    __syncthreads();
    for (int b=tid;b<SBIN;b+=256)
        if (sh[b]) atomicAdd(&g_h1[b], sh[b]);
}

extern "C" __global__ void k_gamma(){
    __shared__ unsigned long long ps[256];
    int tid = threadIdx.x;
    unsigned int loc[8];
    unsigned long long s = 0ull;
    #pragma unroll
    for (int t=0;t<8;t++){ loc[t] = g_h1[tid*8+t]; s += loc[t]; }
    ps[tid] = s; __syncthreads();
    for (int o=1;o<256;o<<=1){
        unsigned long long v = (tid>=o) ? ps[tid-o] : 0ull;
        __syncthreads();
        ps[tid] += v;
        __syncthreads();
    }
    unsigned long long before = ps[tid] - s;
    if (before < SKRANK && ps[tid] >= SKRANK){
        unsigned long long cum = before;
        #pragma unroll
        for (int t=0;t<8;t++){
            if (cum + loc[t] >= SKRANK){
                float frac = (float)(SKRANK - cum) / (float)(loc[t] ? loc[t] : 1u);
                float med = ((float)(tid*8+t) + frac) * 0.5f;
                g_gamma = 1.f/(med + 1e-6f);
                break;
            }
            cum += loc[t];
        }
    }
}

// ---- main d2 GEMM: persistent CTAs, cross-tile cp.async prefetch ----------
__device__ __forceinline__ void d2_issue_loads(uint32_t sbuf, int m0, int n0,
                                               int kc, int tid){
    #pragma unroll
    for (int p=0;p<4;p++){
        int idx = tid + p*256;
        int r = idx>>3, c = idx&7;
        size_t go = (size_t)r*DIM + kc*64 + c*8;
        uint32_t so = (uint32_t)(r*128 + ((c ^ (r&7))<<4));
        cp16(sbuf + so,         g_qhi + (size_t)m0*DIM + go);
        cp16(sbuf + 16384 + so, g_shi + (size_t)n0*DIM + go);
    }
}

extern "C" __global__ __launch_bounds__(256) void k_d2mma(const float* __restrict__ sv){
    extern __shared__ char smem[];
    uint32_t sb = smem_u32(smem);
    float* rAccW = (float*)(smem + SMX_M);
    float* rAccV = rAccW + 128;
    float* sv_s  = rAccV + 128;
    int tid = threadIdx.x, wid = tid>>5, lane = tid&31;
    int wm0 = (wid&1)*64, wn0 = (wid>>1)*32;
    int g = lane>>3, lr = lane&7;
    int G = gridDim.x;
    float gamma = g_gamma;
    int cpar = 0;
    { // prologue: first tile chunk 0
        int t0 = blockIdx.x;
        d2_issue_loads(sb, (t0>>7)*128, (t0&127)*128, 0, tid);
        CP_COMMIT();
    }
    for (int tile = blockIdx.x; tile < NT; tile += G){
        int m0 = (tile>>7)*128, n0 = (tile&127)*128;
        __syncthreads();                          // protect rAcc/sv_s reuse
        ((float*)(smem+SMX_M))[tid] = 0.f;
        if (tid < 128) sv_s[tid] = sv[n0 + tid];
        float acc[4][4][4] = {};
        for (int kc=0;kc<4;kc++){
            uint32_t buf = sb + (uint32_t)((cpar&1)*32768);
            uint32_t nbuf = sb + (uint32_t)(((cpar+1)&1)*32768);
            if (kc < 3){
                d2_issue_loads(nbuf, m0, n0, kc+1, tid);
                CP_COMMIT(); CP_WAIT(1);
            } else {
                int nt = tile + G;
                if (nt < NT){
                    d2_issue_loads(nbuf, (nt>>7)*128, (nt&127)*128, 0, tid);
                    CP_COMMIT(); CP_WAIT(1);
                } else CP_WAIT(0);
            }
            __syncthreads();
            #pragma unroll
            for (int s=0;s<4;s++){
                int cc = s*2 + (g>>1);
                uint32_t a[4][4], bfr[4][2];
                #pragma unroll
                for (int mf=0;mf<4;mf++){
                    int r = wm0 + mf*16 + (g&1)*8 + lr;
                    LDSM4(a[mf][0],a[mf][1],a[mf][2],a[mf][3], buf + r*128 + ((cc ^ (r&7))<<4));
                }
                #pragma unroll
                for (int np=0;np<2;np++){
                    int r = wn0 + np*16 + (g&1)*8 + lr;
                    uint32_t t0,t1,t2,t3;
                    LDSM4(t0,t1,t2,t3, buf + 16384 + r*128 + ((cc ^ (r&7))<<4));
                    bfr[np*2][0]=t0;   bfr[np*2][1]=t2;
                    bfr[np*2+1][0]=t1; bfr[np*2+1][1]=t3;
                }
                #pragma unroll
                for (int mf=0;mf<4;mf++)
                    #pragma unroll
                    for (int nf=0;nf<4;nf++)
                        MMA16816(acc[mf][nf], a[mf], bfr[nf]);
            }
            __syncthreads();
            cpar++;
        }
        int lr0 = wm0 + (lane>>2);
        int cb = wn0 + (lane&3)*2;
        #pragma unroll
        for (int mf=0;mf<4;mf++)
            #pragma unroll
            for (int h=0;h<2;h++){
                int lrow = lr0 + mf*16 + h*8;
                float qn = g_qn[m0 + lrow];
                float sw = 0.f, swv = 0.f;
                #pragma unroll
                for (int nf=0;nf<4;nf++){
                    int col = cb + nf*8;
                    float d0 = fmaxf(qn + g_sn[n0+col]   - 2.f*acc[mf][nf][h*2+0], 0.f);
                    float d1 = fmaxf(qn + g_sn[n0+col+1] - 2.f*acc[mf][nf][h*2+1], 0.f);
                    float w0 = __expf(-gamma*d0);
                    float w1 = __expf(-gamma*d1);
                    sw  += w0 + w1;
                    swv += w0*sv_s[col] + w1*sv_s[col+1];
                }
                sw  += __shfl_xor_sync(0xffffffffu, sw, 1);
                swv += __shfl_xor_sync(0xffffffffu, swv, 1);
                sw  += __shfl_xor_sync(0xffffffffu, sw, 2);
                swv += __shfl_xor_sync(0xffffffffu, swv, 2);
                if ((lane&3)==0){
                    atomicAdd(&rAccW[lrow], sw);
                    atomicAdd(&rAccV[lrow], swv);
                }
            }
        __syncthreads();
        if (tid < 128){
            atomicAdd(&g_accw[m0+tid],  rAccW[tid]);
            atomicAdd(&g_accwv[m0+tid], rAccV[tid]);
        }
    }
}

extern "C" __global__ void k_predfin(float* __restrict__ out){
    int q = blockIdx.x*blockDim.x + threadIdx.x;
    if (q < NQ) out[(size_t)NQ*NCLS + q] = g_accwv[q]/g_accw[q];
}

extern "C" void kernel_launch(void* const* d_in, const int* in_sizes, int n_in,
                              void* d_out, int out_size){
    const float* sf  = (const float*)d_in[0];
    const int*   lab = (const int*)  d_in[1];
    const float* sv  = (const float*)d_in[2];
    const float* qf  = (const float*)d_in[3];
    float* out = (float*)d_out;
    (void)in_sizes; (void)n_in; (void)out_size;

    cudaFuncSetAttribute(k_support, cudaFuncAttributeMaxDynamicSharedMemorySize, SUP_SM);
    cudaFuncSetAttribute(k_d2samp, cudaFuncAttributeMaxDynamicSharedMemorySize, SMT_S);
    cudaFuncSetAttribute(k_d2mma,  cudaFuncAttributeMaxDynamicSharedMemorySize, SMT_M);

    k_zero<<<256,256>>>();
    k_support<<<64,256,SUP_SM>>>(sf, lab);
    k_covgemm<<<dim3(4,4,32),256>>>(sf);
    k_finalize<<<9,256>>>();
    k_logits<<<NQ/4,256>>>(qf, out);
    k_covA<<<64,256>>>();
    k_covB<<<64,256>>>();
    int py=0, pz=1, py2=3, pz2=4;
    for (int it=0; it<4; it++){
        k_mm256<<<dim3(8,8),256>>>(pz, py, 2, 0);
        k_mm256pair<<<dim3(8,8,2),256>>>(py, pz, py2, pz2);
        int t = py; py = py2; py2 = t;
        t = pz; pz = pz2; pz2 = t;
    }
    k_whiten<<<dim3(4,NSUP/128),256>>>(sf, pz, 0);
    k_whiten<<<dim3(4,NQ/128),256>>>(qf, pz, 1);
    k_d2samp<<<dim3(16,8),256,SMT_S>>>();
    k_gamma<<<1,256>>>();
    k_d2mma<<<296,256,SMT_M>>>(sv);
    k_predfin<<<NQ/256,256>>>(out);
}

// round 12
// speedup vs baseline: 1.0292x; 1.0292x over previous
#include <cuda_runtime.h>
#include <cuda_bf16.h>
#include <math.h>
#include <stdint.h>

#define NSUP 16384
#define NQ   8192
#define DIM  256
#define NCLS 64
#define SBIN 2048
#define SKRANK 1048576ULL   /* (1024*2048)/2 */

__device__ float g_psum[NCLS*DIM];
__device__ float g_cnt[NCLS];
__device__ float g_protoT[DIM*NCLS];
__device__ float g_musum[DIM];
__device__ float g_mu[DIM];
__device__ float g_G[DIM*DIM];
__device__ float g_Y[DIM*DIM];
__device__ float g_Z[DIM*DIM];
__device__ float g_T[DIM*DIM];
__device__ float g_Y2[DIM*DIM];
__device__ float g_Z2[DIM*DIM];
__device__ float g_trsum;
__device__ float g_gamma;
__device__ __nv_bfloat16 g_shi[NSUP*DIM];
__device__ __nv_bfloat16 g_qhi[NQ*DIM];
__device__ float g_sn[NSUP];
__device__ float g_qn[NQ];
__device__ float g_accw[NQ];
__device__ float g_accwv[NQ];
__device__ unsigned int g_h1[SBIN];

__device__ __forceinline__ float warp_sum(float v){
    #pragma unroll
    for (int o = 16; o; o >>= 1) v += __shfl_xor_sync(0xffffffffu, v, o);
    return v;
}
__device__ __forceinline__ float warp_max(float v){
    #pragma unroll
    for (int o = 16; o; o >>= 1) v = fmaxf(v, __shfl_xor_sync(0xffffffffu, v, o));
    return v;
}
__device__ __forceinline__ float* bsel(int id){
    switch(id){ case 0: return g_Y; case 1: return g_Z; case 2: return g_T;
                case 3: return g_Y2; default: return g_Z2; }
}
__device__ __forceinline__ uint32_t smem_u32(const void* p){
    uint32_t a;
    asm("{ .reg .u64 t; cvta.to.shared.u64 t, %1; cvt.u32.u64 %0, t; }" : "=r"(a) : "l"(p));
    return a;
}
__device__ __forceinline__ void cp16(uint32_t saddr, const void* gptr){
    asm volatile("cp.async.cg.shared.global [%0], [%1], 16;" :: "r"(saddr), "l"(gptr));
}
#define CP_COMMIT() asm volatile("cp.async.commit_group;" ::: "memory")
#define CP_WAIT(n)  asm volatile("cp.async.wait_group %0;" :: "n"(n) : "memory")
#define LDSM4(r0,r1,r2,r3,addr) \
    asm volatile("ldmatrix.sync.aligned.m8n8.x4.shared.b16 {%0,%1,%2,%3}, [%4];" \
        : "=r"(r0),"=r"(r1),"=r"(r2),"=r"(r3) : "r"(addr))
#define MMA16816(c,a,b) \
    asm volatile("mma.sync.aligned.m16n8k16.row.col.f32.bf16.bf16.f32 " \
        "{%0,%1,%2,%3},{%4,%5,%6,%7},{%8,%9},{%0,%1,%2,%3};" \
        : "+f"((c)[0]),"+f"((c)[1]),"+f"((c)[2]),"+f"((c)[3]) \
        : "r"((a)[0]),"r"((a)[1]),"r"((a)[2]),"r"((a)[3]), "r"((b)[0]),"r"((b)[1]))

// ---------------------------------------------------------------------------
extern "C" __global__ void k_zero(){
    int i = blockIdx.x*blockDim.x + threadIdx.x, st = gridDim.x*blockDim.x;
    for (int e=i; e<NCLS*DIM; e+=st) g_psum[e]=0.f;
    for (int e=i; e<NCLS;     e+=st) g_cnt[e]=0.f;
    for (int e=i; e<DIM;      e+=st) g_musum[e]=0.f;
    for (int e=i; e<DIM*DIM;  e+=st) g_G[e]=0.f;
    for (int e=i; e<SBIN;     e+=st) g_h1[e]=0u;
    for (int e=i; e<NSUP;     e+=st) g_sn[e]=0.f;
    for (int e=i; e<NQ;       e+=st){ g_qn[e]=0.f; g_accw[e]=0.f; g_accwv[e]=0.f; }
    if (i==0) g_trsum = 0.f;
}

// smem class-sum accumulation (64 blocks x 256 rows)
#define SUP_SM ((NCLS*DIM + NCLS)*4)
extern "C" __global__ __launch_bounds__(256) void k_support(
        const float* __restrict__ sf, const int* __restrict__ lab){
    extern __shared__ float sp[];            // [NCLS*DIM] + [NCLS]
    float* sc = sp + NCLS*DIM;
    int tid = threadIdx.x, w = tid>>5, lane = tid&31;
    for (int i=tid; i<NCLS*DIM; i+=256) sp[i]=0.f;
    if (tid < NCLS) sc[tid]=0.f;
    __syncthreads();
    int r0 = blockIdx.x * (NSUP/64);
    float msum[8];
    #pragma unroll
    for (int t=0;t<8;t++) msum[t]=0.f;
    for (int r = r0+w; r < r0 + NSUP/64; r += 8){
        const float* row = sf + (size_t)r*DIM;
        float x[8], ss=0.f;
        #pragma unroll
        for (int t=0;t<8;t++){ x[t]=row[lane+32*t]; ss += x[t]*x[t]; }
        ss = warp_sum(ss);
        float inv = 1.f / fmaxf(sqrtf(ss), 1e-8f);
        int lb = lab[r];
        #pragma unroll
        for (int t=0;t<8;t++){
            msum[t] += x[t];
            atomicAdd(&sp[lb*DIM + lane + 32*t], x[t]*inv);
        }
        if (!lane) atomicAdd(&sc[lb], 1.f);
    }
    #pragma unroll
    for (int t=0;t<8;t++) atomicAdd(&g_musum[lane+32*t], msum[t]);
    __syncthreads();
    for (int i=tid; i<NCLS*DIM; i+=256){
        float v = sp[i];
        if (v != 0.f) atomicAdd(&g_psum[i], v);
    }
    if (tid < NCLS && sc[tid] != 0.f) atomicAdd(&g_cnt[tid], sc[tid]);
}

// block 0: mu; blocks 1..8: 8 classes each (warp per class)
extern "C" __global__ void k_finalize(){
    int tid = threadIdx.x, w = tid>>5, lane = tid&31;
    if (blockIdx.x == 0){
        if (tid < DIM) g_mu[tid] = g_musum[tid] * (1.f/NSUP);
        return;
    }
    int c = (blockIdx.x-1)*8 + w;
    float ic = 1.f / fmaxf(g_cnt[c], 1.f);
    float v[8], ss=0.f;
    #pragma unroll
    for (int t=0;t<8;t++){ v[t]=g_psum[c*DIM+lane+32*t]*ic; ss+=v[t]*v[t]; }
    ss = warp_sum(ss);
    float inv = 1.f / fmaxf(sqrtf(ss), 1e-8f);
    #pragma unroll
    for (int t=0;t<8;t++) g_protoT[(lane+32*t)*NCLS + c] = v[t]*inv;
}

extern "C" __global__ __launch_bounds__(256) void k_logits(
        const float* __restrict__ qf, float* __restrict__ out){
    __shared__ float sq[4][260];
    __shared__ float sred[8], sinv[4], smax[8], ssum[8];
    int tid = threadIdx.x, w = tid>>5, lane = tid&31;
    int q0 = blockIdx.x*4;
    #pragma unroll
    for (int p=0;p<4;p++) sq[p][tid] = qf[(size_t)(q0+p)*DIM + tid];
    __syncthreads();
    { int row = w>>1, base = (w&1)*128;
      float s=0.f;
      #pragma unroll
      for (int t=0;t<4;t++){ float v=sq[row][base+lane+32*t]; s+=v*v; }
      s = warp_sum(s);
      if (!lane) sred[w]=s; }
    __syncthreads();
    if (tid<4) sinv[tid] = 1.f / fmaxf(sqrtf(sred[2*tid]+sred[2*tid+1]), 1e-8f);
    __syncthreads();
    int c = tid&63, qi = tid>>6;
    float acc = 0.f;
    #pragma unroll 8
    for (int k=0;k<DIM;k++) acc = fmaf(sq[qi][k], g_protoT[k*NCLS+c], acc);
    acc *= sinv[qi];
    float m = warp_max(acc);
    if (!lane) smax[w]=m;
    __syncthreads();
    m = fmaxf(smax[qi*2], smax[qi*2+1]);
    float e = expf(acc - m);
    float s = warp_sum(e);
    if (!lane) ssum[w]=s;
    __syncthreads();
    float lse = m + logf(ssum[qi*2]+ssum[qi*2+1]);
    out[(size_t)(q0+qi)*NCLS + c] = acc - lse;
}

extern "C" __global__ __launch_bounds__(256) void k_covgemm(const float* __restrict__ X){
    __shared__ float Xa[16][68], Xb[16][68];
    int tid = threadIdx.x, tx = tid&15, ty = tid>>4;
    int i0 = blockIdx.y*64, j0 = blockIdx.x*64;
    int chunk = NSUP/gridDim.z, rb = blockIdx.z*chunk;
    float acc[4][4] = {};
    for (int r = rb; r < rb+chunk; r += 16){
        #pragma unroll
        for (int p=0;p<4;p++){
            int lin = tid + p*256, rr = lin>>6, c = lin&63;
            Xa[rr][c] = X[(size_t)(r+rr)*DIM + i0 + c];
            Xb[rr][c] = X[(size_t)(r+rr)*DIM + j0 + c];
        }
        __syncthreads();
        #pragma unroll
        for (int kk=0;kk<16;kk++){
            float a[4], b[4];
            #pragma unroll
            for (int u=0;u<4;u++){ a[u]=Xa[kk][ty*4+u]; b[u]=Xb[kk][tx*4+u]; }
            #pragma unroll
            for (int u=0;u<4;u++)
                #pragma unroll
                for (int v=0;v<4;v++) acc[u][v]=fmaf(a[u],b[v],acc[u][v]);
        }
        __syncthreads();
    }
    #pragma unroll
    for (int u=0;u<4;u++)
        #pragma unroll
        for (int v=0;v<4;v++)
            atomicAdd(&g_G[(i0+ty*4+u)*DIM + j0+tx*4+v], acc[u][v]);
}

extern "C" __global__ void k_covA(){
    __shared__ float red[256];
    int tid = threadIdx.x;
    float tr = 0.f;
    #pragma unroll
    for (int p=0;p<4;p++){
        int e = blockIdx.x*1024 + p*256 + tid;
        int i = e>>8, j = e&255;
        float v = (g_G[e] - (float)NSUP*g_mu[i]*g_mu[j]) * (1.f/(NSUP-1));
        if (i==j){ v += 1e-4f; tr += v; }
        g_T[e] = v;
    }
    red[tid]=tr; __syncthreads();
    for (int s=128;s;s>>=1){ if(tid<s) red[tid]+=red[tid+s]; __syncthreads(); }
    if (!tid && red[0] != 0.f) atomicAdd(&g_trsum, red[0]);
}

extern "C" __global__ void k_covB(){
    float ic = (float)DIM / g_trsum;
    int tid = threadIdx.x;
    #pragma unroll
    for (int p=0;p<4;p++){
        int e = blockIdx.x*1024 + p*256 + tid;
        int i = e>>8, j = e&255;
        g_Y[e] = g_T[e]*ic;
        g_Z[e] = (i==j)?1.f:0.f;
    }
}

extern "C" __global__ __launch_bounds__(256) void k_mm256(int ia,int ib,int ic,int mode){
    const float* A = bsel(ia); const float* B = bsel(ib); float* C = bsel(ic);
    __shared__ float As[32][33], Bs[32][33];
    int tid = threadIdx.x, tx = tid&15, ty = tid>>4;
    int j0 = blockIdx.x*32, i0 = blockIdx.y*32;
    float a00=0,a01=0,a10=0,a11=0;
    for (int k0=0;k0<DIM;k0+=32){
        #pragma unroll
        for (int p=0;p<4;p++){
            int lin = tid+p*256, r = lin>>5, c = lin&31;
            As[r][c] = A[(i0+r)*DIM + k0+c];
            Bs[r][c] = B[(k0+r)*DIM + j0+c];
        }
        __syncthreads();
        #pragma unroll
        for (int kk=0;kk<32;kk++){
            float x0=As[ty*2][kk], x1=As[ty*2+1][kk];
            float y0=Bs[kk][tx*2], y1=Bs[kk][tx*2+1];
            a00=fmaf(x0,y0,a00); a01=fmaf(x0,y1,a01);
            a10=fmaf(x1,y0,a10); a11=fmaf(x1,y1,a11);
        }
        __syncthreads();
    }
    int i = i0+ty*2, j = j0+tx*2;
    float o[2][2] = {{a00,a01},{a10,a11}};
    #pragma unroll
    for (int u=0;u<2;u++)
        #pragma unroll
        for (int v=0;v<2;v++){
            float val = o[u][v];
            if (mode==0) val = ((i+u==j+v)?1.5f:0.f) - 0.5f*val;
            C[(i+u)*DIM + j+v] = val;
        }
}

extern "C" __global__ __launch_bounds__(256) void k_mm256pair(int py,int pz,int py2,int pz2){
    const float* A; const float* B; float* C;
    if (blockIdx.z == 0){ A = bsel(py); B = g_T; C = bsel(py2); }
    else                { A = g_T; B = bsel(pz); C = bsel(pz2); }
    __shared__ float As[32][33], Bs[32][33];
    int tid = threadIdx.x, tx = tid&15, ty = tid>>4;
    int j0 = blockIdx.x*32, i0 = blockIdx.y*32;
    float a00=0,a01=0,a10=0,a11=0;
    for (int k0=0;k0<DIM;k0+=32){
        #pragma unroll
        for (int p=0;p<4;p++){
            int lin = tid+p*256, r = lin>>5, c = lin&31;
            As[r][c] = A[(i0+r)*DIM + k0+c];
            Bs[r][c] = B[(k0+r)*DIM + j0+c];
        }
        __syncthreads();
        #pragma unroll
        for (int kk=0;kk<32;kk++){
            float x0=As[ty*2][kk], x1=As[ty*2+1][kk];
            float y0=Bs[kk][tx*2], y1=Bs[kk][tx*2+1];
            a00=fmaf(x0,y0,a00); a01=fmaf(x0,y1,a01);
            a10=fmaf(x1,y0,a10); a11=fmaf(x1,y1,a11);
        }
        __syncthreads();
    }
    int i = i0+ty*2, j = j0+tx*2;
    C[i*DIM + j]       = a00;
    C[i*DIM + j+1]     = a01;
    C[(i+1)*DIM + j]   = a10;
    C[(i+1)*DIM + j+1] = a11;
}

// whiten + fused muZ + fused bf16 convert + fused row-norm partials
extern "C" __global__ __launch_bounds__(256) void k_whiten(
        const float* __restrict__ Xin, int zid, int wsel){
    const float* M = bsel(zid);
    __nv_bfloat16* Bout = wsel ? g_qhi : g_shi;
    float* Nout = wsel ? g_qn : g_sn;
    __shared__ float Xs[16][132], Ms[16][68];
    __shared__ float muzp[4][64];
    __shared__ float muz[64];
    int tid = threadIdx.x, tx = tid&15, ty = tid>>4;
    int m0 = blockIdx.y*128, j0 = blockIdx.x*64;
    { int col = tid>>2, part = tid&3;
      float s = 0.f;
      #pragma unroll 16
      for (int k=part*64; k<part*64+64; k++) s = fmaf(g_mu[k], M[k*DIM + j0 + col], s);
      muzp[part][col] = s; }
    __syncthreads();
    if (tid < 64) muz[tid] = muzp[0][tid]+muzp[1][tid]+muzp[2][tid]+muzp[3][tid];
    float acc[8][4] = {};
    for (int k0=0;k0<DIM;k0+=16){
        #pragma unroll
        for (int p=0;p<2;p++){
            int lin = tid+p*256, m = lin>>2, c4 = (lin&3)*4;
            float4 v = *(const float4*)(Xin + (size_t)(m0+m)*DIM + k0 + c4);
            Xs[c4][m]=v.x; Xs[c4+1][m]=v.y; Xs[c4+2][m]=v.z; Xs[c4+3][m]=v.w;
        }
        { int r = tid>>4, c4 = (tid&15)*4;
          *(float4*)&Ms[r][c4] = *(const float4*)(M + (k0+r)*DIM + j0 + c4); }
        __syncthreads();
        #pragma unroll
        for (int kk=0;kk<16;kk++){
            float av[8], bv[4];
            #pragma unroll
            for (int u=0;u<8;u++) av[u]=Xs[kk][ty*8+u];
            #pragma unroll
            for (int v=0;v<4;v++) bv[v]=Ms[kk][tx*4+v];
            #pragma unroll
            for (int u=0;u<8;u++)
                #pragma unroll
                for (int v=0;v<4;v++) acc[u][v]=fmaf(av[u],bv[v],acc[u][v]);
        }
        __syncthreads();
    }
    float rs = sqrtf((float)DIM / g_trsum);
    float mz[4];
    #pragma unroll
    for (int v=0;v<4;v++) mz[v] = muz[tx*4+v];
    #pragma unroll
    for (int u=0;u<8;u++){
        float vv[4]; float ss = 0.f;
        #pragma unroll
        for (int v=0;v<4;v++){ vv[v]=(acc[u][v]-mz[v])*rs; ss += vv[v]*vv[v]; }
        __nv_bfloat16 h[4];
        #pragma unroll
        for (int v=0;v<4;v++) h[v] = __float2bfloat16_rn(vv[v]);
        int row = m0 + ty*8 + u;
        *(ushort4*)(Bout + (size_t)row*DIM + j0 + tx*4) =
            make_ushort4(*(unsigned short*)&h[0], *(unsigned short*)&h[1],
                         *(unsigned short*)&h[2], *(unsigned short*)&h[3]);
        atomicAdd(&Nout[row], ss);
    }
}

// ---- sample d2 GEMM for gamma ---------------------------------------------
#define SMA   0
#define SMB   16384
#define SMX_S 32768
#define SMT_S 40960
#define SMX_M 65536
#define SMT_M 67072

extern "C" __global__ __launch_bounds__(256) void k_d2samp(){
    extern __shared__ char smem[];
    uint32_t sb = smem_u32(smem);
    unsigned int* sh = (unsigned int*)(smem + SMX_S);
    int tid = threadIdx.x, wid = tid>>5, lane = tid&31;
    int m0 = blockIdx.y*128, n0 = blockIdx.x*128;
    int wm0 = (wid&1)*64, wn0 = (wid>>1)*32;
    for (int b=tid;b<SBIN;b+=256) sh[b]=0u;
    float acc[4][4][4] = {};
    int g = lane>>3, lr = lane&7;
    for (int kc=0;kc<4;kc++){
        #pragma unroll
        for (int p=0;p<4;p++){
            int idx = tid + p*256;
            int r = idx>>3, c = idx&7;
            size_t go = (size_t)r*DIM + kc*64 + c*8;
            uint32_t so = (uint32_t)(r*128 + ((c ^ (r&7))<<4));
            *(uint4*)(smem+SMA+so) = *(const uint4*)(g_qhi + (size_t)m0*DIM + go);
            *(uint4*)(smem+SMB+so) = *(const uint4*)(g_shi + (size_t)n0*DIM + go);
        }
        __syncthreads();
        #pragma unroll
        for (int s=0;s<4;s++){
            int cc = s*2 + (g>>1);
            uint32_t a[4][4], bfr[4][2];
            #pragma unroll
            for (int mf=0;mf<4;mf++){
                int r = wm0 + mf*16 + (g&1)*8 + lr;
                LDSM4(a[mf][0],a[mf][1],a[mf][2],a[mf][3], sb + SMA + r*128 + ((cc ^ (r&7))<<4));
            }
            #pragma unroll
            for (int np=0;np<2;np++){
                int r = wn0 + np*16 + (g&1)*8 + lr;
                uint32_t t0,t1,t2,t3;
                LDSM4(t0,t1,t2,t3, sb + SMB + r*128 + ((cc ^ (r&7))<<4));
                bfr[np*2][0]=t0;   bfr[np*2][1]=t2;
                bfr[np*2+1][0]=t1; bfr[np*2+1][1]=t3;
            }
            #pragma unroll
            for (int mf=0;mf<4;mf++)
                #pragma unroll
                for (int nf=0;nf<4;nf++)
                    MMA16816(acc[mf][nf], a[mf], bfr[nf]);
        }
        __syncthreads();
    }
    int rbase = m0 + wm0 + (lane>>2);
    int cbase = n0 + wn0 + (lane&3)*2;
    #pragma unroll
    for (int mf=0;mf<4;mf++)
        #pragma unroll
        for (int h=0;h<2;h++){
            float qn = g_qn[rbase + mf*16 + h*8];
            #pragma unroll
            for (int nf=0;nf<4;nf++){
                int col = cbase + nf*8;
                float v0 = fmaxf(qn + g_sn[col]   - 2.f*acc[mf][nf][h*2+0], 0.f);
                float v1 = fmaxf(qn + g_sn[col+1] - 2.f*acc[mf][nf][h*2+1], 0.f);
                int b0=(int)(v0*2.0f); if(b0>SBIN-1)b0=SBIN-1;
                int b1=(int)(v1*2.0f); if(b1>SBIN-1)b1=SBIN-1;
                atomicAdd(&sh[b0],1u); atomicAdd(&sh[b1],1u);
            }
        }
    __syncthreads();
    for (int b=tid;b<SBIN;b+=256)
        if (sh[b]) atomicAdd(&g_h1[b], sh[b]);
}

extern "C" __global__ void k_gamma(){
    __shared__ unsigned long long ps[256];
    int tid = threadIdx.x;
    unsigned int loc[8];
    unsigned long long s = 0ull;
    #pragma unroll
    for (int t=0;t<8;t++){ loc[t] = g_h1[tid*8+t]; s += loc[t]; }
    ps[tid] = s; __syncthreads();
    for (int o=1;o<256;o<<=1){
        unsigned long long v = (tid>=o) ? ps[tid-o] : 0ull;
        __syncthreads();
        ps[tid] += v;
        __syncthreads();
    }
    unsigned long long before = ps[tid] - s;
    if (before < SKRANK && ps[tid] >= SKRANK){
        unsigned long long cum = before;
        #pragma unroll
        for (int t=0;t<8;t++){
            if (cum + loc[t] >= SKRANK){
                float frac = (float)(SKRANK - cum) / (float)(loc[t] ? loc[t] : 1u);
                float med = ((float)(tid*8+t) + frac) * 0.5f;
                g_gamma = 1.f/(med + 1e-6f);
                break;
            }
            cum += loc[t];
        }
    }
}

// ---- main d2 GEMM: cp.async double-buffered, fused softmax reduction -------
__device__ __forceinline__ void d2_issue_loads(uint32_t sbuf, int m0, int n0,
                                               int kc, int tid){
    #pragma unroll
    for (int p=0;p<4;p++){
        int idx = tid + p*256;
        int r = idx>>3, c = idx&7;
        size_t go = (size_t)r*DIM + kc*64 + c*8;
        uint32_t so = (uint32_t)(r*128 + ((c ^ (r&7))<<4));
        cp16(sbuf + so,         g_qhi + (size_t)m0*DIM + go);
        cp16(sbuf + 16384 + so, g_shi + (size_t)n0*DIM + go);
    }
}

extern "C" __global__ __launch_bounds__(256) void k_d2mma(const float* __restrict__ sv){
    extern __shared__ char smem[];
    uint32_t sb = smem_u32(smem);
    float* rAccW = (float*)(smem + SMX_M);
    float* rAccV = rAccW + 128;
    float* sv_s  = rAccV + 128;
    int tid = threadIdx.x, wid = tid>>5, lane = tid&31;
    int m0 = blockIdx.y*128, n0 = blockIdx.x*128;
    int wm0 = (wid&1)*64, wn0 = (wid>>1)*32;
    ((float*)(smem+SMX_M))[tid] = 0.f;       // zeroes rAccW+rAccV
    if (tid < 128) sv_s[tid] = sv[n0 + tid];
    float acc[4][4][4] = {};
    int g = lane>>3, lr = lane&7;

    d2_issue_loads(sb, m0, n0, 0, tid);
    CP_COMMIT();
    for (int kc=0;kc<4;kc++){
        uint32_t buf = sb + (uint32_t)((kc&1)*32768);
        if (kc < 3){
            d2_issue_loads(sb + (uint32_t)(((kc+1)&1)*32768), m0, n0, kc+1, tid);
            CP_COMMIT();
            CP_WAIT(1);
        } else {
            CP_WAIT(0);
        }
        __syncthreads();
        #pragma unroll
        for (int s=0;s<4;s++){
            int cc = s*2 + (g>>1);
            uint32_t a[4][4], bfr[4][2];
            #pragma unroll
            for (int mf=0;mf<4;mf++){
                int r = wm0 + mf*16 + (g&1)*8 + lr;
                LDSM4(a[mf][0],a[mf][1],a[mf][2],a[mf][3], buf + r*128 + ((cc ^ (r&7))<<4));
            }
            #pragma unroll
            for (int np=0;np<2;np++){
                int r = wn0 + np*16 + (g&1)*8 + lr;
                uint32_t t0,t1,t2,t3;
                LDSM4(t0,t1,t2,t3, buf + 16384 + r*128 + ((cc ^ (r&7))<<4));
                bfr[np*2][0]=t0;   bfr[np*2][1]=t2;
                bfr[np*2+1][0]=t1; bfr[np*2+1][1]=t3;
            }
            #pragma unroll
            for (int mf=0;mf<4;mf++)
                #pragma unroll
                for (int nf=0;nf<4;nf++)
                    MMA16816(acc[mf][nf], a[mf], bfr[nf]);
        }
        __syncthreads();
    }
    float gamma = g_gamma;
    int lr0 = wm0 + (lane>>2);
    int cb = wn0 + (lane&3)*2;
    #pragma unroll
    for (int mf=0;mf<4;mf++)
        #pragma unroll
        for (int h=0;h<2;h++){
            int lrow = lr0 + mf*16 + h*8;
            float qn = g_qn[m0 + lrow];
            float sw = 0.f, swv = 0.f;
            #pragma unroll
            for (int nf=0;nf<4;nf++){
                int col = cb + nf*8;
                float d0 = fmaxf(qn + g_sn[n0+col]   - 2.f*acc[mf][nf][h*2+0], 0.f);
                float d1 = fmaxf(qn + g_sn[n0+col+1] - 2.f*acc[mf][nf][h*2+1], 0.f);
                float w0 = __expf(-gamma*d0);
                float w1 = __expf(-gamma*d1);
                sw  += w0 + w1;
                swv += w0*sv_s[col] + w1*sv_s[col+1];
            }
            sw  += __shfl_xor_sync(0xffffffffu, sw, 1);
            swv += __shfl_xor_sync(0xffffffffu, swv, 1);
            sw  += __shfl_xor_sync(0xffffffffu, sw, 2);
            swv += __shfl_xor_sync(0xffffffffu, swv, 2);
            if ((lane&3)==0){
                atomicAdd(&rAccW[lrow], sw);
                atomicAdd(&rAccV[lrow], swv);
            }
        }
    __syncthreads();
    if (tid < 128){
        atomicAdd(&g_accw[m0+tid],  rAccW[tid]);
        atomicAdd(&g_accwv[m0+tid], rAccV[tid]);
    }
}

extern "C" __global__ void k_predfin(float* __restrict__ out){
    int q = blockIdx.x*blockDim.x + threadIdx.x;
    if (q < NQ) out[(size_t)NQ*NCLS + q] = g_accwv[q]/g_accw[q];
}

extern "C" void kernel_launch(void* const* d_in, const int* in_sizes, int n_in,
                              void* d_out, int out_size){
    const float* sf  = (const float*)d_in[0];
    const int*   lab = (const int*)  d_in[1];
    const float* sv  = (const float*)d_in[2];
    const float* qf  = (const float*)d_in[3];
    float* out = (float*)d_out;
    (void)in_sizes; (void)n_in; (void)out_size;

    cudaFuncSetAttribute(k_support, cudaFuncAttributeMaxDynamicSharedMemorySize, SUP_SM);
    cudaFuncSetAttribute(k_d2samp, cudaFuncAttributeMaxDynamicSharedMemorySize, SMT_S);
    cudaFuncSetAttribute(k_d2mma,  cudaFuncAttributeMaxDynamicSharedMemorySize, SMT_M);

    k_zero<<<256,256>>>();
    k_support<<<64,256,SUP_SM>>>(sf, lab);
    k_covgemm<<<dim3(4,4,32),256>>>(sf);
    k_finalize<<<9,256>>>();
    k_logits<<<NQ/4,256>>>(qf, out);
    k_covA<<<64,256>>>();
    k_covB<<<64,256>>>();
    int py=0, pz=1, py2=3, pz2=4;
    for (int it=0; it<4; it++){
        k_mm256<<<dim3(8,8),256>>>(pz, py, 2, 0);
        k_mm256pair<<<dim3(8,8,2),256>>>(py, pz, py2, pz2);
        int t = py; py = py2; py2 = t;
        t = pz; pz = pz2; pz2 = t;
    }
    k_whiten<<<dim3(4,NSUP/128),256>>>(sf, pz, 0);
    k_whiten<<<dim3(4,NQ/128),256>>>(qf, pz, 1);
    k_d2samp<<<dim3(16,8),256,SMT_S>>>();
    k_gamma<<<1,256>>>();
    k_d2mma<<<dim3(NSUP/128,NQ/128),256,SMT_M>>>(sv);
    k_predfin<<<NQ/256,256>>>(out);
}

// round 13
// speedup vs baseline: 1.0698x; 1.0395x over previous
#include <cuda_runtime.h>
#include <cuda_bf16.h>
#include <math.h>
#include <stdint.h>

#define NSUP 16384
#define NQ   8192
#define DIM  256
#define NCLS 64
#define SBIN 2048
#define SKRANK 1048576ULL   /* (1024*2048)/2 */

__device__ float g_psum[NCLS*DIM];
__device__ float g_cnt[NCLS];
__device__ float g_protoT[DIM*NCLS];
__device__ float g_musum[DIM];
__device__ float g_mu[DIM];
__device__ float g_G[DIM*DIM];
__device__ float g_Y[DIM*DIM];
__device__ float g_Z[DIM*DIM];
__device__ float g_T[DIM*DIM];
__device__ float g_Y2[DIM*DIM];
__device__ float g_Z2[DIM*DIM];
__device__ float g_trsum;
__device__ float g_gamma;
__device__ __nv_bfloat16 g_shi[NSUP*DIM];
__device__ __nv_bfloat16 g_qhi[NQ*DIM];
__device__ float g_sn[NSUP];
__device__ float g_qn[NQ];
__device__ float g_accw[NQ];
__device__ float g_accwv[NQ];
__device__ unsigned int g_h1[SBIN];

__device__ __forceinline__ float warp_sum(float v){
    #pragma unroll
    for (int o = 16; o; o >>= 1) v += __shfl_xor_sync(0xffffffffu, v, o);
    return v;
}
__device__ __forceinline__ float warp_max(float v){
    #pragma unroll
    for (int o = 16; o; o >>= 1) v = fmaxf(v, __shfl_xor_sync(0xffffffffu, v, o));
    return v;
}
__device__ __forceinline__ float* bsel(int id){
    switch(id){ case 0: return g_Y; case 1: return g_Z; case 2: return g_T;
                case 3: return g_Y2; default: return g_Z2; }
}
__device__ __forceinline__ uint32_t smem_u32(const void* p){
    uint32_t a;
    asm("{ .reg .u64 t; cvta.to.shared.u64 t, %1; cvt.u32.u64 %0, t; }" : "=r"(a) : "l"(p));
    return a;
}
__device__ __forceinline__ void cp16(uint32_t saddr, const void* gptr){
    asm volatile("cp.async.cg.shared.global [%0], [%1], 16;" :: "r"(saddr), "l"(gptr));
}
#define CP_COMMIT() asm volatile("cp.async.commit_group;" ::: "memory")
#define CP_WAIT(n)  asm volatile("cp.async.wait_group %0;" :: "n"(n) : "memory")
#define LDSM4(r0,r1,r2,r3,addr) \
    asm volatile("ldmatrix.sync.aligned.m8n8.x4.shared.b16 {%0,%1,%2,%3}, [%4];" \
        : "=r"(r0),"=r"(r1),"=r"(r2),"=r"(r3) : "r"(addr))
#define MMA16816(c,a,b) \
    asm volatile("mma.sync.aligned.m16n8k16.row.col.f32.bf16.bf16.f32 " \
        "{%0,%1,%2,%3},{%4,%5,%6,%7},{%8,%9},{%0,%1,%2,%3};" \
        : "+f"((c)[0]),"+f"((c)[1]),"+f"((c)[2]),"+f"((c)[3]) \
        : "r"((a)[0]),"r"((a)[1]),"r"((a)[2]),"r"((a)[3]), "r"((b)[0]),"r"((b)[1]))

// ---------------------------------------------------------------------------
extern "C" __global__ void k_zero(){
    int i = blockIdx.x*blockDim.x + threadIdx.x, st = gridDim.x*blockDim.x;
    for (int e=i; e<NCLS*DIM; e+=st) g_psum[e]=0.f;
    for (int e=i; e<NCLS;     e+=st) g_cnt[e]=0.f;
    for (int e=i; e<DIM;      e+=st) g_musum[e]=0.f;
    for (int e=i; e<DIM*DIM;  e+=st) g_G[e]=0.f;
    for (int e=i; e<SBIN;     e+=st) g_h1[e]=0u;
    for (int e=i; e<NSUP;     e+=st) g_sn[e]=0.f;
    for (int e=i; e<NQ;       e+=st){ g_qn[e]=0.f; g_accw[e]=0.f; g_accwv[e]=0.f; }
    if (i==0) g_trsum = 0.f;
}

// R10 version: global atomics, 128 blocks
extern "C" __global__ __launch_bounds__(256) void k_support(
        const float* __restrict__ sf, const int* __restrict__ lab){
    int w = threadIdx.x>>5, lane = threadIdx.x&31;
    int r0 = blockIdx.x * (NSUP/gridDim.x);
    float msum[8];
    #pragma unroll
    for (int t=0;t<8;t++) msum[t]=0.f;
    for (int r = r0+w; r < r0 + NSUP/gridDim.x; r += 8){
        const float* row = sf + (size_t)r*DIM;
        float x[8], ss=0.f;
        #pragma unroll
        for (int t=0;t<8;t++){ x[t]=row[lane+32*t]; ss += x[t]*x[t]; }
        ss = warp_sum(ss);
        float inv = 1.f / fmaxf(sqrtf(ss), 1e-8f);
        int lb = lab[r];
        #pragma unroll
        for (int t=0;t<8;t++){
            msum[t] += x[t];
            atomicAdd(&g_psum[lb*DIM + lane + 32*t], x[t]*inv);
        }
        if (!lane) atomicAdd(&g_cnt[lb], 1.f);
    }
    #pragma unroll
    for (int t=0;t<8;t++) atomicAdd(&g_musum[lane+32*t], msum[t]);
}

// block 0: mu; blocks 1..8: 8 classes each (warp per class)
extern "C" __global__ void k_finalize(){
    int tid = threadIdx.x, w = tid>>5, lane = tid&31;
    if (blockIdx.x == 0){
        if (tid < DIM) g_mu[tid] = g_musum[tid] * (1.f/NSUP);
        return;
    }
    int c = (blockIdx.x-1)*8 + w;
    float ic = 1.f / fmaxf(g_cnt[c], 1.f);
    float v[8], ss=0.f;
    #pragma unroll
    for (int t=0;t<8;t++){ v[t]=g_psum[c*DIM+lane+32*t]*ic; ss+=v[t]*v[t]; }
    ss = warp_sum(ss);
    float inv = 1.f / fmaxf(sqrtf(ss), 1e-8f);
    #pragma unroll
    for (int t=0;t<8;t++) g_protoT[(lane+32*t)*NCLS + c] = v[t]*inv;
}

extern "C" __global__ __launch_bounds__(256) void k_logits(
        const float* __restrict__ qf, float* __restrict__ out){
    __shared__ float sq[4][260];
    __shared__ float sred[8], sinv[4], smax[8], ssum[8];
    int tid = threadIdx.x, w = tid>>5, lane = tid&31;
    int q0 = blockIdx.x*4;
    #pragma unroll
    for (int p=0;p<4;p++) sq[p][tid] = qf[(size_t)(q0+p)*DIM + tid];
    __syncthreads();
    { int row = w>>1, base = (w&1)*128;
      float s=0.f;
      #pragma unroll
      for (int t=0;t<4;t++){ float v=sq[row][base+lane+32*t]; s+=v*v; }
      s = warp_sum(s);
      if (!lane) sred[w]=s; }
    __syncthreads();
    if (tid<4) sinv[tid] = 1.f / fmaxf(sqrtf(sred[2*tid]+sred[2*tid+1]), 1e-8f);
    __syncthreads();
    int c = tid&63, qi = tid>>6;
    float acc = 0.f;
    #pragma unroll 8
    for (int k=0;k<DIM;k++) acc = fmaf(sq[qi][k], g_protoT[k*NCLS+c], acc);
    acc *= sinv[qi];
    float m = warp_max(acc);
    if (!lane) smax[w]=m;
    __syncthreads();
    m = fmaxf(smax[qi*2], smax[qi*2+1]);
    float e = expf(acc - m);
    float s = warp_sum(e);
    if (!lane) ssum[w]=s;
    __syncthreads();
    float lse = m + logf(ssum[qi*2]+ssum[qi*2+1]);
    out[(size_t)(q0+qi)*NCLS + c] = acc - lse;
}

extern "C" __global__ __launch_bounds__(256) void k_covgemm(const float* __restrict__ X){
    __shared__ float Xa[16][68], Xb[16][68];
    int tid = threadIdx.x, tx = tid&15, ty = tid>>4;
    int i0 = blockIdx.y*64, j0 = blockIdx.x*64;
    int chunk = NSUP/gridDim.z, rb = blockIdx.z*chunk;
    float acc[4][4] = {};
    for (int r = rb; r < rb+chunk; r += 16){
        #pragma unroll
        for (int p=0;p<4;p++){
            int lin = tid + p*256, rr = lin>>6, c = lin&63;
            Xa[rr][c] = X[(size_t)(r+rr)*DIM + i0 + c];
            Xb[rr][c] = X[(size_t)(r+rr)*DIM + j0 + c];
        }
        __syncthreads();
        #pragma unroll
        for (int kk=0;kk<16;kk++){
            float a[4], b[4];
            #pragma unroll
            for (int u=0;u<4;u++){ a[u]=Xa[kk][ty*4+u]; b[u]=Xb[kk][tx*4+u]; }
            #pragma unroll
            for (int u=0;u<4;u++)
                #pragma unroll
                for (int v=0;v<4;v++) acc[u][v]=fmaf(a[u],b[v],acc[u][v]);
        }
        __syncthreads();
    }
    #pragma unroll
    for (int u=0;u<4;u++)
        #pragma unroll
        for (int v=0;v<4;v++)
            atomicAdd(&g_G[(i0+ty*4+u)*DIM + j0+tx*4+v], acc[u][v]);
}

extern "C" __global__ void k_covA(){
    __shared__ float red[256];
    int tid = threadIdx.x;
    float tr = 0.f;
    #pragma unroll
    for (int p=0;p<4;p++){
        int e = blockIdx.x*1024 + p*256 + tid;
        int i = e>>8, j = e&255;
        float v = (g_G[e] - (float)NSUP*g_mu[i]*g_mu[j]) * (1.f/(NSUP-1));
        if (i==j){ v += 1e-4f; tr += v; }
        g_T[e] = v;
    }
    red[tid]=tr; __syncthreads();
    for (int s=128;s;s>>=1){ if(tid<s) red[tid]+=red[tid+s]; __syncthreads(); }
    if (!tid && red[0] != 0.f) atomicAdd(&g_trsum, red[0]);
}

// normalize + init: Y0 = Anorm, Z slot <- T0 = 1.5I - 0.5*Y0
// (NS iteration 1 done algebraically; bit-exact vs matmul against identity)
extern "C" __global__ void k_covB(){
    float ic = (float)DIM / g_trsum;
    int tid = threadIdx.x;
    #pragma unroll
    for (int p=0;p<4;p++){
        int e = blockIdx.x*1024 + p*256 + tid;
        int i = e>>8, j = e&255;
        float y0 = g_T[e]*ic;
        g_Y[e] = y0;
        g_Z[e] = ((i==j)?1.5f:0.f) - 0.5f*y0;   // T0 == Z1
    }
}

extern "C" __global__ __launch_bounds__(256) void k_mm256(int ia,int ib,int ic,int mode){
    const float* A = bsel(ia); const float* B = bsel(ib); float* C = bsel(ic);
    __shared__ float As[32][33], Bs[32][33];
    int tid = threadIdx.x, tx = tid&15, ty = tid>>4;
    int j0 = blockIdx.x*32, i0 = blockIdx.y*32;
    float a00=0,a01=0,a10=0,a11=0;
    for (int k0=0;k0<DIM;k0+=32){
        #pragma unroll
        for (int p=0;p<4;p++){
            int lin = tid+p*256, r = lin>>5, c = lin&31;
            As[r][c] = A[(i0+r)*DIM + k0+c];
            Bs[r][c] = B[(k0+r)*DIM + j0+c];
        }
        __syncthreads();
        #pragma unroll
        for (int kk=0;kk<32;kk++){
            float x0=As[ty*2][kk], x1=As[ty*2+1][kk];
            float y0=Bs[kk][tx*2], y1=Bs[kk][tx*2+1];
            a00=fmaf(x0,y0,a00); a01=fmaf(x0,y1,a01);
            a10=fmaf(x1,y0,a10); a11=fmaf(x1,y1,a11);
        }
        __syncthreads();
    }
    int i = i0+ty*2, j = j0+tx*2;
    float o[2][2] = {{a00,a01},{a10,a11}};
    #pragma unroll
    for (int u=0;u<2;u++)
        #pragma unroll
        for (int v=0;v<2;v++){
            float val = o[u][v];
            if (mode==0) val = ((i+u==j+v)?1.5f:0.f) - 0.5f*val;
            C[(i+u)*DIM + j+v] = val;
        }
}

extern "C" __global__ __launch_bounds__(256) void k_mm256pair(int py,int pz,int py2,int pz2){
    const float* A; const float* B; float* C;
    if (blockIdx.z == 0){ A = bsel(py); B = g_T; C = bsel(py2); }
    else                { A = g_T; B = bsel(pz); C = bsel(pz2); }
    __shared__ float As[32][33], Bs[32][33];
    int tid = threadIdx.x, tx = tid&15, ty = tid>>4;
    int j0 = blockIdx.x*32, i0 = blockIdx.y*32;
    float a00=0,a01=0,a10=0,a11=0;
    for (int k0=0;k0<DIM;k0+=32){
        #pragma unroll
        for (int p=0;p<4;p++){
            int lin = tid+p*256, r = lin>>5, c = lin&31;
            As[r][c] = A[(i0+r)*DIM + k0+c];
            Bs[r][c] = B[(k0+r)*DIM + j0+c];
        }
        __syncthreads();
        #pragma unroll
        for (int kk=0;kk<32;kk++){
            float x0=As[ty*2][kk], x1=As[ty*2+1][kk];
            float y0=Bs[kk][tx*2], y1=Bs[kk][tx*2+1];
            a00=fmaf(x0,y0,a00); a01=fmaf(x0,y1,a01);
            a10=fmaf(x1,y0,a10); a11=fmaf(x1,y1,a11);
        }
        __syncthreads();
    }
    int i = i0+ty*2, j = j0+tx*2;
    C[i*DIM + j]       = a00;
    C[i*DIM + j+1]     = a01;
    C[(i+1)*DIM + j]   = a10;
    C[(i+1)*DIM + j+1] = a11;
}

// whiten + fused muZ + fused bf16 convert + fused row-norm partials
extern "C" __global__ __launch_bounds__(256) void k_whiten(
        const float* __restrict__ Xin, int zid, int wsel){
    const float* M = bsel(zid);
    __nv_bfloat16* Bout = wsel ? g_qhi : g_shi;
    float* Nout = wsel ? g_qn : g_sn;
    __shared__ float Xs[16][132], Ms[16][68];
    __shared__ float muzp[4][64];
    __shared__ float muz[64];
    int tid = threadIdx.x, tx = tid&15, ty = tid>>4;
    int m0 = blockIdx.y*128, j0 = blockIdx.x*64;
    { int col = tid>>2, part = tid&3;
      float s = 0.f;
      #pragma unroll 16
      for (int k=part*64; k<part*64+64; k++) s = fmaf(g_mu[k], M[k*DIM + j0 + col], s);
      muzp[part][col] = s; }
    __syncthreads();
    if (tid < 64) muz[tid] = muzp[0][tid]+muzp[1][tid]+muzp[2][tid]+muzp[3][tid];
    float acc[8][4] = {};
    for (int k0=0;k0<DIM;k0+=16){
        #pragma unroll
        for (int p=0;p<2;p++){
            int lin = tid+p*256, m = lin>>2, c4 = (lin&3)*4;
            float4 v = *(const float4*)(Xin + (size_t)(m0+m)*DIM + k0 + c4);
            Xs[c4][m]=v.x; Xs[c4+1][m]=v.y; Xs[c4+2][m]=v.z; Xs[c4+3][m]=v.w;
        }
        { int r = tid>>4, c4 = (tid&15)*4;
          *(float4*)&Ms[r][c4] = *(const float4*)(M + (k0+r)*DIM + j0 + c4); }
        __syncthreads();
        #pragma unroll
        for (int kk=0;kk<16;kk++){
            float av[8], bv[4];
            #pragma unroll
            for (int u=0;u<8;u++) av[u]=Xs[kk][ty*8+u];
            #pragma unroll
            for (int v=0;v<4;v++) bv[v]=Ms[kk][tx*4+v];
            #pragma unroll
            for (int u=0;u<8;u++)
                #pragma unroll
                for (int v=0;v<4;v++) acc[u][v]=fmaf(av[u],bv[v],acc[u][v]);
        }
        __syncthreads();
    }
    float rs = sqrtf((float)DIM / g_trsum);
    float mz[4];
    #pragma unroll
    for (int v=0;v<4;v++) mz[v] = muz[tx*4+v];
    #pragma unroll
    for (int u=0;u<8;u++){
        float vv[4]; float ss = 0.f;
        #pragma unroll
        for (int v=0;v<4;v++){ vv[v]=(acc[u][v]-mz[v])*rs; ss += vv[v]*vv[v]; }
        __nv_bfloat16 h[4];
        #pragma unroll
        for (int v=0;v<4;v++) h[v] = __float2bfloat16_rn(vv[v]);
        int row = m0 + ty*8 + u;
        *(ushort4*)(Bout + (size_t)row*DIM + j0 + tx*4) =
            make_ushort4(*(unsigned short*)&h[0], *(unsigned short*)&h[1],
                         *(unsigned short*)&h[2], *(unsigned short*)&h[3]);
        atomicAdd(&Nout[row], ss);
    }
}

// ---- sample d2 GEMM for gamma ---------------------------------------------
#define SMA   0
#define SMB   16384
#define SMX_S 32768
#define SMT_S 40960
#define SMX_M 65536
#define SMT_M 67072

extern "C" __global__ __launch_bounds__(256) void k_d2samp(){
    extern __shared__ char smem[];
    uint32_t sb = smem_u32(smem);
    unsigned int* sh = (unsigned int*)(smem + SMX_S);
    int tid = threadIdx.x, wid = tid>>5, lane = tid&31;
    int m0 = blockIdx.y*128, n0 = blockIdx.x*128;
    int wm0 = (wid&1)*64, wn0 = (wid>>1)*32;
    for (int b=tid;b<SBIN;b+=256) sh[b]=0u;
    float acc[4][4][4] = {};
    int g = lane>>3, lr = lane&7;
    for (int kc=0;kc<4;kc++){
        #pragma unroll
        for (int p=0;p<4;p++){
            int idx = tid + p*256;
            int r = idx>>3, c = idx&7;
            size_t go = (size_t)r*DIM + kc*64 + c*8;
            uint32_t so = (uint32_t)(r*128 + ((c ^ (r&7))<<4));
            *(uint4*)(smem+SMA+so) = *(const uint4*)(g_qhi + (size_t)m0*DIM + go);
            *(uint4*)(smem+SMB+so) = *(const uint4*)(g_shi + (size_t)n0*DIM + go);
        }
        __syncthreads();
        #pragma unroll
        for (int s=0;s<4;s++){
            int cc = s*2 + (g>>1);
            uint32_t a[4][4], bfr[4][2];
            #pragma unroll
            for (int mf=0;mf<4;mf++){
                int r = wm0 + mf*16 + (g&1)*8 + lr;
                LDSM4(a[mf][0],a[mf][1],a[mf][2],a[mf][3], sb + SMA + r*128 + ((cc ^ (r&7))<<4));
            }
            #pragma unroll
            for (int np=0;np<2;np++){
                int r = wn0 + np*16 + (g&1)*8 + lr;
                uint32_t t0,t1,t2,t3;
                LDSM4(t0,t1,t2,t3, sb + SMB + r*128 + ((cc ^ (r&7))<<4));
                bfr[np*2][0]=t0;   bfr[np*2][1]=t2;
                bfr[np*2+1][0]=t1; bfr[np*2+1][1]=t3;
            }
            #pragma unroll
            for (int mf=0;mf<4;mf++)
                #pragma unroll
                for (int nf=0;nf<4;nf++)
                    MMA16816(acc[mf][nf], a[mf], bfr[nf]);
        }
        __syncthreads();
    }
    int rbase = m0 + wm0 + (lane>>2);
    int cbase = n0 + wn0 + (lane&3)*2;
    #pragma unroll
    for (int mf=0;mf<4;mf++)
        #pragma unroll
        for (int h=0;h<2;h++){
            float qn = g_qn[rbase + mf*16 + h*8];
            #pragma unroll
            for (int nf=0;nf<4;nf++){
                int col = cbase + nf*8;
                float v0 = fmaxf(qn + g_sn[col]   - 2.f*acc[mf][nf][h*2+0], 0.f);
                float v1 = fmaxf(qn + g_sn[col+1] - 2.f*acc[mf][nf][h*2+1], 0.f);
                int b0=(int)(v0*2.0f); if(b0>SBIN-1)b0=SBIN-1;
                int b1=(int)(v1*2.0f); if(b1>SBIN-1)b1=SBIN-1;
                atomicAdd(&sh[b0],1u); atomicAdd(&sh[b1],1u);
            }
        }
    __syncthreads();
    for (int b=tid;b<SBIN;b+=256)
        if (sh[b]) atomicAdd(&g_h1[b], sh[b]);
}

extern "C" __global__ void k_gamma(){
    __shared__ unsigned long long ps[256];
    int tid = threadIdx.x;
    unsigned int loc[8];
    unsigned long long s = 0ull;
    #pragma unroll
    for (int t=0;t<8;t++){ loc[t] = g_h1[tid*8+t]; s += loc[t]; }
    ps[tid] = s; __syncthreads();
    for (int o=1;o<256;o<<=1){
        unsigned long long v = (tid>=o) ? ps[tid-o] : 0ull;
        __syncthreads();
        ps[tid] += v;
        __syncthreads();
    }
    unsigned long long before = ps[tid] - s;
    if (before < SKRANK && ps[tid] >= SKRANK){
        unsigned long long cum = before;
        #pragma unroll
        for (int t=0;t<8;t++){
            if (cum + loc[t] >= SKRANK){
                float frac = (float)(SKRANK - cum) / (float)(loc[t] ? loc[t] : 1u);
                float med = ((float)(tid*8+t) + frac) * 0.5f;
                g_gamma = 1.f/(med + 1e-6f);
                break;
            }
            cum += loc[t];
        }
    }
}

// ---- main d2 GEMM: cp.async double-buffered, fused softmax reduction -------
__device__ __forceinline__ void d2_issue_loads(uint32_t sbuf, int m0, int n0,
                                               int kc, int tid){
    #pragma unroll
    for (int p=0;p<4;p++){
        int idx = tid + p*256;
        int r = idx>>3, c = idx&7;
        size_t go = (size_t)r*DIM + kc*64 + c*8;
        uint32_t so = (uint32_t)(r*128 + ((c ^ (r&7))<<4));
        cp16(sbuf + so,         g_qhi + (size_t)m0*DIM + go);
        cp16(sbuf + 16384 + so, g_shi + (size_t)n0*DIM + go);
    }
}

extern "C" __global__ __launch_bounds__(256) void k_d2mma(const float* __restrict__ sv){
    extern __shared__ char smem[];
    uint32_t sb = smem_u32(smem);
    float* rAccW = (float*)(smem + SMX_M);
    float* rAccV = rAccW + 128;
    float* sv_s  = rAccV + 128;
    int tid = threadIdx.x, wid = tid>>5, lane = tid&31;
    int m0 = blockIdx.y*128, n0 = blockIdx.x*128;
    int wm0 = (wid&1)*64, wn0 = (wid>>1)*32;
    ((float*)(smem+SMX_M))[tid] = 0.f;       // zeroes rAccW+rAccV
    if (tid < 128) sv_s[tid] = sv[n0 + tid];
    float acc[4][4][4] = {};
    int g = lane>>3, lr = lane&7;

    d2_issue_loads(sb, m0, n0, 0, tid);
    CP_COMMIT();
    for (int kc=0;kc<4;kc++){
        uint32_t buf = sb + (uint32_t)((kc&1)*32768);
        if (kc < 3){
            d2_issue_loads(sb + (uint32_t)(((kc+1)&1)*32768), m0, n0, kc+1, tid);
            CP_COMMIT();
            CP_WAIT(1);
        } else {
            CP_WAIT(0);
        }
        __syncthreads();
        #pragma unroll
        for (int s=0;s<4;s++){
            int cc = s*2 + (g>>1);
            uint32_t a[4][4], bfr[4][2];
            #pragma unroll
            for (int mf=0;mf<4;mf++){
                int r = wm0 + mf*16 + (g&1)*8 + lr;
                LDSM4(a[mf][0],a[mf][1],a[mf][2],a[mf][3], buf + r*128 + ((cc ^ (r&7))<<4));
            }
            #pragma unroll
            for (int np=0;np<2;np++){
                int r = wn0 + np*16 + (g&1)*8 + lr;
                uint32_t t0,t1,t2,t3;
                LDSM4(t0,t1,t2,t3, buf + 16384 + r*128 + ((cc ^ (r&7))<<4));
                bfr[np*2][0]=t0;   bfr[np*2][1]=t2;
                bfr[np*2+1][0]=t1; bfr[np*2+1][1]=t3;
            }
            #pragma unroll
            for (int mf=0;mf<4;mf++)
                #pragma unroll
                for (int nf=0;nf<4;nf++)
                    MMA16816(acc[mf][nf], a[mf], bfr[nf]);
        }
        __syncthreads();
    }
    float gamma = g_gamma;
    int lr0 = wm0 + (lane>>2);
    int cb = wn0 + (lane&3)*2;
    #pragma unroll
    for (int mf=0;mf<4;mf++)
        #pragma unroll
        for (int h=0;h<2;h++){
            int lrow = lr0 + mf*16 + h*8;
            float qn = g_qn[m0 + lrow];
            float sw = 0.f, swv = 0.f;
            #pragma unroll
            for (int nf=0;nf<4;nf++){
                int col = cb + nf*8;
                float d0 = fmaxf(qn + g_sn[n0+col]   - 2.f*acc[mf][nf][h*2+0], 0.f);
                float d1 = fmaxf(qn + g_sn[n0+col+1] - 2.f*acc[mf][nf][h*2+1], 0.f);
                float w0 = __expf(-gamma*d0);
                float w1 = __expf(-gamma*d1);
                sw  += w0 + w1;
                swv += w0*sv_s[col] + w1*sv_s[col+1];
            }
            sw  += __shfl_xor_sync(0xffffffffu, sw, 1);
            swv += __shfl_xor_sync(0xffffffffu, swv, 1);
            sw  += __shfl_xor_sync(0xffffffffu, sw, 2);
            swv += __shfl_xor_sync(0xffffffffu, swv, 2);
            if ((lane&3)==0){
                atomicAdd(&rAccW[lrow], sw);
                atomicAdd(&rAccV[lrow], swv);
            }
        }
    __syncthreads();
    if (tid < 128){
        atomicAdd(&g_accw[m0+tid],  rAccW[tid]);
        atomicAdd(&g_accwv[m0+tid], rAccV[tid]);
    }
}

extern "C" __global__ void k_predfin(float* __restrict__ out){
    int q = blockIdx.x*blockDim.x + threadIdx.x;
    if (q < NQ) out[(size_t)NQ*NCLS + q] = g_accwv[q]/g_accw[q];
}

extern "C" void kernel_launch(void* const* d_in, const int* in_sizes, int n_in,
                              void* d_out, int out_size){
    const float* sf  = (const float*)d_in[0];
    const int*   lab = (const int*)  d_in[1];
    const float* sv  = (const float*)d_in[2];
    const float* qf  = (const float*)d_in[3];
    float* out = (float*)d_out;
    (void)in_sizes; (void)n_in; (void)out_size;

    cudaFuncSetAttribute(k_d2samp, cudaFuncAttributeMaxDynamicSharedMemorySize, SMT_S);
    cudaFuncSetAttribute(k_d2mma,  cudaFuncAttributeMaxDynamicSharedMemorySize, SMT_M);

    k_zero<<<256,256>>>();
    k_support<<<128,256>>>(sf, lab);
    k_covgemm<<<dim3(4,4,32),256>>>(sf);
    k_finalize<<<9,256>>>();
    k_logits<<<NQ/4,256>>>(qf, out);
    k_covA<<<64,256>>>();
    k_covB<<<64,256>>>();
    // NS iter 1 (algebraic): Y0 in slot0, T0==Z1 in slot1.  Y1 = Y0 @ T0 -> slot3
    k_mm256<<<dim3(8,8),256>>>(0, 1, 3, 1);
    // NS iters 2..4 (full): state Y in slot3, Z in slot1
    int py=3, pz=1, py2=0, pz2=4;
    for (int it=0; it<3; it++){
        k_mm256<<<dim3(8,8),256>>>(pz, py, 2, 0);
        k_mm256pair<<<dim3(8,8,2),256>>>(py, pz, py2, pz2);
        int t = py; py = py2; py2 = t;
        t = pz; pz = pz2; pz2 = t;
    }
    k_whiten<<<dim3(4,NSUP/128),256>>>(sf, pz, 0);
    k_whiten<<<dim3(4,NQ/128),256>>>(qf, pz, 1);
    k_d2samp<<<dim3(16,8),256,SMT_S>>>();
    k_gamma<<<1,256>>>();
    k_d2mma<<<dim3(NSUP/128,NQ/128),256,SMT_M>>>(sv);
    k_predfin<<<NQ/256,256>>>(out);
}

// round 14
// speedup vs baseline: 1.1393x; 1.0650x over previous
#include <cuda_runtime.h>
#include <cuda_bf16.h>
#include <math.h>
#include <stdint.h>

#define NSUP 16384
#define NQ   8192
#define DIM  256
#define NCLS 64
#define SBIN 2048
#define SKRANK 1048576ULL   /* (1024*2048)/2 */

__device__ float g_psum[NCLS*DIM];
__device__ float g_cnt[NCLS];
__device__ float g_protoT[DIM*NCLS];
__device__ float g_musum[DIM];
__device__ float g_mu[DIM];
__device__ float g_G[DIM*DIM];
__device__ float g_Y[DIM*DIM];
__device__ float g_Z[DIM*DIM];
__device__ float g_T[DIM*DIM];
__device__ float g_Y2[DIM*DIM];
__device__ float g_Z2[DIM*DIM];
__device__ float g_trsum;
__device__ float g_gamma;
__device__ __nv_bfloat16 g_shi[NSUP*DIM];
__device__ __nv_bfloat16 g_qhi[NQ*DIM];
__device__ float g_sn[NSUP];
__device__ float g_qn[NQ];
__device__ float g_accw[NQ];
__device__ float g_accwv[NQ];
__device__ unsigned int g_h1[SBIN];

__device__ __forceinline__ float warp_sum(float v){
    #pragma unroll
    for (int o = 16; o; o >>= 1) v += __shfl_xor_sync(0xffffffffu, v, o);
    return v;
}
__device__ __forceinline__ float warp_max(float v){
    #pragma unroll
    for (int o = 16; o; o >>= 1) v = fmaxf(v, __shfl_xor_sync(0xffffffffu, v, o));
    return v;
}
__device__ __forceinline__ float* bsel(int id){
    switch(id){ case 0: return g_Y; case 1: return g_Z; case 2: return g_T;
                case 3: return g_Y2; default: return g_Z2; }
}
__device__ __forceinline__ uint32_t smem_u32(const void* p){
    uint32_t a;
    asm("{ .reg .u64 t; cvta.to.shared.u64 t, %1; cvt.u32.u64 %0, t; }" : "=r"(a) : "l"(p));
    return a;
}
__device__ __forceinline__ void cp16(uint32_t saddr, const void* gptr){
    asm volatile("cp.async.cg.shared.global [%0], [%1], 16;" :: "r"(saddr), "l"(gptr));
}
#define CP_COMMIT() asm volatile("cp.async.commit_group;" ::: "memory")
#define CP_WAIT(n)  asm volatile("cp.async.wait_group %0;" :: "n"(n) : "memory")
#define LDSM4(r0,r1,r2,r3,addr) \
    asm volatile("ldmatrix.sync.aligned.m8n8.x4.shared.b16 {%0,%1,%2,%3}, [%4];" \
        : "=r"(r0),"=r"(r1),"=r"(r2),"=r"(r3) : "r"(addr))
#define MMA16816(c,a,b) \
    asm volatile("mma.sync.aligned.m16n8k16.row.col.f32.bf16.bf16.f32 " \
        "{%0,%1,%2,%3},{%4,%5,%6,%7},{%8,%9},{%0,%1,%2,%3};" \
        : "+f"((c)[0]),"+f"((c)[1]),"+f"((c)[2]),"+f"((c)[3]) \
        : "r"((a)[0]),"r"((a)[1]),"r"((a)[2]),"r"((a)[3]), "r"((b)[0]),"r"((b)[1]))

// ---------------------------------------------------------------------------
extern "C" __global__ void k_zero(){
    int i = blockIdx.x*blockDim.x + threadIdx.x, st = gridDim.x*blockDim.x;
    for (int e=i; e<NCLS*DIM; e+=st) g_psum[e]=0.f;
    for (int e=i; e<NCLS;     e+=st) g_cnt[e]=0.f;
    for (int e=i; e<DIM;      e+=st) g_musum[e]=0.f;
    for (int e=i; e<DIM*DIM;  e+=st) g_G[e]=0.f;
    for (int e=i; e<SBIN;     e+=st) g_h1[e]=0u;
    for (int e=i; e<NSUP;     e+=st) g_sn[e]=0.f;
    for (int e=i; e<NQ;       e+=st){ g_qn[e]=0.f; g_accw[e]=0.f; g_accwv[e]=0.f; }
    if (i==0) g_trsum = 0.f;
}

extern "C" __global__ __launch_bounds__(256) void k_support(
        const float* __restrict__ sf, const int* __restrict__ lab){
    int w = threadIdx.x>>5, lane = threadIdx.x&31;
    int r0 = blockIdx.x * (NSUP/gridDim.x);
    float msum[8];
    #pragma unroll
    for (int t=0;t<8;t++) msum[t]=0.f;
    for (int r = r0+w; r < r0 + NSUP/gridDim.x; r += 8){
        const float* row = sf + (size_t)r*DIM;
        float x[8], ss=0.f;
        #pragma unroll
        for (int t=0;t<8;t++){ x[t]=row[lane+32*t]; ss += x[t]*x[t]; }
        ss = warp_sum(ss);
        float inv = 1.f / fmaxf(sqrtf(ss), 1e-8f);
        int lb = lab[r];
        #pragma unroll
        for (int t=0;t<8;t++){
            msum[t] += x[t];
            atomicAdd(&g_psum[lb*DIM + lane + 32*t], x[t]*inv);
        }
        if (!lane) atomicAdd(&g_cnt[lb], 1.f);
    }
    #pragma unroll
    for (int t=0;t<8;t++) atomicAdd(&g_musum[lane+32*t], msum[t]);
}

extern "C" __global__ void k_finalize(){
    int tid = threadIdx.x, w = tid>>5, lane = tid&31;
    if (blockIdx.x == 0){
        if (tid < DIM) g_mu[tid] = g_musum[tid] * (1.f/NSUP);
        return;
    }
    int c = (blockIdx.x-1)*8 + w;
    float ic = 1.f / fmaxf(g_cnt[c], 1.f);
    float v[8], ss=0.f;
    #pragma unroll
    for (int t=0;t<8;t++){ v[t]=g_psum[c*DIM+lane+32*t]*ic; ss+=v[t]*v[t]; }
    ss = warp_sum(ss);
    float inv = 1.f / fmaxf(sqrtf(ss), 1e-8f);
    #pragma unroll
    for (int t=0;t<8;t++) g_protoT[(lane+32*t)*NCLS + c] = v[t]*inv;
}

extern "C" __global__ __launch_bounds__(256) void k_logits(
        const float* __restrict__ qf, float* __restrict__ out){
    __shared__ float sq[4][260];
    __shared__ float sred[8], sinv[4], smax[8], ssum[8];
    int tid = threadIdx.x, w = tid>>5, lane = tid&31;
    int q0 = blockIdx.x*4;
    #pragma unroll
    for (int p=0;p<4;p++) sq[p][tid] = qf[(size_t)(q0+p)*DIM + tid];
    __syncthreads();
    { int row = w>>1, base = (w&1)*128;
      float s=0.f;
      #pragma unroll
      for (int t=0;t<4;t++){ float v=sq[row][base+lane+32*t]; s+=v*v; }
      s = warp_sum(s);
      if (!lane) sred[w]=s; }
    __syncthreads();
    if (tid<4) sinv[tid] = 1.f / fmaxf(sqrtf(sred[2*tid]+sred[2*tid+1]), 1e-8f);
    __syncthreads();
    int c = tid&63, qi = tid>>6;
    float acc = 0.f;
    #pragma unroll 8
    for (int k=0;k<DIM;k++) acc = fmaf(sq[qi][k], g_protoT[k*NCLS+c], acc);
    acc *= sinv[qi];
    float m = warp_max(acc);
    if (!lane) smax[w]=m;
    __syncthreads();
    m = fmaxf(smax[qi*2], smax[qi*2+1]);
    float e = expf(acc - m);
    float s = warp_sum(e);
    if (!lane) ssum[w]=s;
    __syncthreads();
    float lse = m + logf(ssum[qi*2]+ssum[qi*2+1]);
    out[(size_t)(q0+qi)*NCLS + c] = acc - lse;
}

// symmetric: only upper-triangle 64x64 block pairs (10 of 16)
extern "C" __global__ __launch_bounds__(256) void k_covgemm(const float* __restrict__ X){
    const int pi[10] = {0,0,0,0,1,1,1,2,2,3};
    const int pj[10] = {0,1,2,3,1,2,3,2,3,3};
    __shared__ float Xa[16][68], Xb[16][68];
    int tid = threadIdx.x, tx = tid&15, ty = tid>>4;
    int i0 = pi[blockIdx.x]*64, j0 = pj[blockIdx.x]*64;
    int chunk = NSUP/gridDim.z, rb = blockIdx.z*chunk;
    float acc[4][4] = {};
    for (int r = rb; r < rb+chunk; r += 16){
        #pragma unroll
        for (int p=0;p<4;p++){
            int lin = tid + p*256, rr = lin>>6, c = lin&63;
            Xa[rr][c] = X[(size_t)(r+rr)*DIM + i0 + c];
            Xb[rr][c] = X[(size_t)(r+rr)*DIM + j0 + c];
        }
        __syncthreads();
        #pragma unroll
        for (int kk=0;kk<16;kk++){
            float a[4], b[4];
            #pragma unroll
            for (int u=0;u<4;u++){ a[u]=Xa[kk][ty*4+u]; b[u]=Xb[kk][tx*4+u]; }
            #pragma unroll
            for (int u=0;u<4;u++)
                #pragma unroll
                for (int v=0;v<4;v++) acc[u][v]=fmaf(a[u],b[v],acc[u][v]);
        }
        __syncthreads();
    }
    #pragma unroll
    for (int u=0;u<4;u++)
        #pragma unroll
        for (int v=0;v<4;v++)
            atomicAdd(&g_G[(i0+ty*4+u)*DIM + j0+tx*4+v], acc[u][v]);
}

// mirror lower triangle from upper
extern "C" __global__ void k_covA(){
    __shared__ float red[256];
    int tid = threadIdx.x;
    float tr = 0.f;
    #pragma unroll
    for (int p=0;p<4;p++){
        int e = blockIdx.x*1024 + p*256 + tid;
        int i = e>>8, j = e&255;
        int src = (i<=j) ? e : (j*DIM + i);
        float v = (g_G[src] - (float)NSUP*g_mu[i]*g_mu[j]) * (1.f/(NSUP-1));
        if (i==j){ v += 1e-4f; tr += v; }
        g_T[e] = v;
    }
    red[tid]=tr; __syncthreads();
    for (int s=128;s;s>>=1){ if(tid<s) red[tid]+=red[tid+s]; __syncthreads(); }
    if (!tid && red[0] != 0.f) atomicAdd(&g_trsum, red[0]);
}

// normalize + init: Y0 = Anorm, Z slot <- T0 = 1.5I - 0.5*Y0 (algebraic NS iter 1)
extern "C" __global__ void k_covB(){
    float ic = (float)DIM / g_trsum;
    int tid = threadIdx.x;
    #pragma unroll
    for (int p=0;p<4;p++){
        int e = blockIdx.x*1024 + p*256 + tid;
        int i = e>>8, j = e&255;
        float y0 = g_T[e]*ic;
        g_Y[e] = y0;
        g_Z[e] = ((i==j)?1.5f:0.f) - 0.5f*y0;   // T0 == Z1
    }
}

extern "C" __global__ __launch_bounds__(256) void k_mm256(int ia,int ib,int ic,int mode){
    const float* A = bsel(ia); const float* B = bsel(ib); float* C = bsel(ic);
    __shared__ float As[32][33], Bs[32][33];
    int tid = threadIdx.x, tx = tid&15, ty = tid>>4;
    int j0 = blockIdx.x*32, i0 = blockIdx.y*32;
    float a00=0,a01=0,a10=0,a11=0;
    for (int k0=0;k0<DIM;k0+=32){
        #pragma unroll
        for (int p=0;p<4;p++){
            int lin = tid+p*256, r = lin>>5, c = lin&31;
            As[r][c] = A[(i0+r)*DIM + k0+c];
            Bs[r][c] = B[(k0+r)*DIM + j0+c];
        }
        __syncthreads();
        #pragma unroll
        for (int kk=0;kk<32;kk++){
            float x0=As[ty*2][kk], x1=As[ty*2+1][kk];
            float y0=Bs[kk][tx*2], y1=Bs[kk][tx*2+1];
            a00=fmaf(x0,y0,a00); a01=fmaf(x0,y1,a01);
            a10=fmaf(x1,y0,a10); a11=fmaf(x1,y1,a11);
        }
        __syncthreads();
    }
    int i = i0+ty*2, j = j0+tx*2;
    float o[2][2] = {{a00,a01},{a10,a11}};
    #pragma unroll
    for (int u=0;u<2;u++)
        #pragma unroll
        for (int v=0;v<2;v++){
            float val = o[u][v];
            if (mode==0) val = ((i+u==j+v)?1.5f:0.f) - 0.5f*val;
            C[(i+u)*DIM + j+v] = val;
        }
}

extern "C" __global__ __launch_bounds__(256) void k_mm256pair(int py,int pz,int py2,int pz2){
    const float* A; const float* B; float* C;
    if (blockIdx.z == 0){ A = bsel(py); B = g_T; C = bsel(py2); }
    else                { A = g_T; B = bsel(pz); C = bsel(pz2); }
    __shared__ float As[32][33], Bs[32][33];
    int tid = threadIdx.x, tx = tid&15, ty = tid>>4;
    int j0 = blockIdx.x*32, i0 = blockIdx.y*32;
    float a00=0,a01=0,a10=0,a11=0;
    for (int k0=0;k0<DIM;k0+=32){
        #pragma unroll
        for (int p=0;p<4;p++){
            int lin = tid+p*256, r = lin>>5, c = lin&31;
            As[r][c] = A[(i0+r)*DIM + k0+c];
            Bs[r][c] = B[(k0+r)*DIM + j0+c];
        }
        __syncthreads();
        #pragma unroll
        for (int kk=0;kk<32;kk++){
            float x0=As[ty*2][kk], x1=As[ty*2+1][kk];
            float y0=Bs[kk][tx*2], y1=Bs[kk][tx*2+1];
            a00=fmaf(x0,y0,a00); a01=fmaf(x0,y1,a01);
            a10=fmaf(x1,y0,a10); a11=fmaf(x1,y1,a11);
        }
        __syncthreads();
    }
    int i = i0+ty*2, j = j0+tx*2;
    C[i*DIM + j]       = a00;
    C[i*DIM + j+1]     = a01;
    C[(i+1)*DIM + j]   = a10;
    C[(i+1)*DIM + j+1] = a11;
}

// whiten + fused muZ + fused bf16 convert + fused row-norm partials
extern "C" __global__ __launch_bounds__(256) void k_whiten(
        const float* __restrict__ Xin, int zid, int wsel){
    const float* M = bsel(zid);
    __nv_bfloat16* Bout = wsel ? g_qhi : g_shi;
    float* Nout = wsel ? g_qn : g_sn;
    __shared__ float Xs[16][132], Ms[16][68];
    __shared__ float muzp[4][64];
    __shared__ float muz[64];
    int tid = threadIdx.x, tx = tid&15, ty = tid>>4;
    int m0 = blockIdx.y*128, j0 = blockIdx.x*64;
    { int col = tid>>2, part = tid&3;
      float s = 0.f;
      #pragma unroll 16
      for (int k=part*64; k<part*64+64; k++) s = fmaf(g_mu[k], M[k*DIM + j0 + col], s);
      muzp[part][col] = s; }
    __syncthreads();
    if (tid < 64) muz[tid] = muzp[0][tid]+muzp[1][tid]+muzp[2][tid]+muzp[3][tid];
    float acc[8][4] = {};
    for (int k0=0;k0<DIM;k0+=16){
        #pragma unroll
        for (int p=0;p<2;p++){
            int lin = tid+p*256, m = lin>>2, c4 = (lin&3)*4;
            float4 v = *(const float4*)(Xin + (size_t)(m0+m)*DIM + k0 + c4);
            Xs[c4][m]=v.x; Xs[c4+1][m]=v.y; Xs[c4+2][m]=v.z; Xs[c4+3][m]=v.w;
        }
        { int r = tid>>4, c4 = (tid&15)*4;
          *(float4*)&Ms[r][c4] = *(const float4*)(M + (k0+r)*DIM + j0 + c4); }
        __syncthreads();
        #pragma unroll
        for (int kk=0;kk<16;kk++){
            float av[8], bv[4];
            #pragma unroll
            for (int u=0;u<8;u++) av[u]=Xs[kk][ty*8+u];
            #pragma unroll
            for (int v=0;v<4;v++) bv[v]=Ms[kk][tx*4+v];
            #pragma unroll
            for (int u=0;u<8;u++)
                #pragma unroll
                for (int v=0;v<4;v++) acc[u][v]=fmaf(av[u],bv[v],acc[u][v]);
        }
        __syncthreads();
    }
    float rs = sqrtf((float)DIM / g_trsum);
    float mz[4];
    #pragma unroll
    for (int v=0;v<4;v++) mz[v] = muz[tx*4+v];
    #pragma unroll
    for (int u=0;u<8;u++){
        float vv[4]; float ss = 0.f;
        #pragma unroll
        for (int v=0;v<4;v++){ vv[v]=(acc[u][v]-mz[v])*rs; ss += vv[v]*vv[v]; }
        __nv_bfloat16 h[4];
        #pragma unroll
        for (int v=0;v<4;v++) h[v] = __float2bfloat16_rn(vv[v]);
        int row = m0 + ty*8 + u;
        *(ushort4*)(Bout + (size_t)row*DIM + j0 + tx*4) =
            make_ushort4(*(unsigned short*)&h[0], *(unsigned short*)&h[1],
                         *(unsigned short*)&h[2], *(unsigned short*)&h[3]);
        atomicAdd(&Nout[row], ss);
    }
}

// ---- sample d2 GEMM for gamma ---------------------------------------------
#define SMA   0
#define SMB   16384
#define SMX_S 32768
#define SMT_S 40960
#define SMX_M 65536
#define SMT_M 67072

extern "C" __global__ __launch_bounds__(256) void k_d2samp(){
    extern __shared__ char smem[];
    uint32_t sb = smem_u32(smem);
    unsigned int* sh = (unsigned int*)(smem + SMX_S);
    int tid = threadIdx.x, wid = tid>>5, lane = tid&31;
    int m0 = blockIdx.y*128, n0 = blockIdx.x*128;
    int wm0 = (wid&1)*64, wn0 = (wid>>1)*32;
    for (int b=tid;b<SBIN;b+=256) sh[b]=0u;
    float acc[4][4][4] = {};
    int g = lane>>3, lr = lane&7;
    for (int kc=0;kc<4;kc++){
        #pragma unroll
        for (int p=0;p<4;p++){
            int idx = tid + p*256;
            int r = idx>>3, c = idx&7;
            size_t go = (size_t)r*DIM + kc*64 + c*8;
            uint32_t so = (uint32_t)(r*128 + ((c ^ (r&7))<<4));
            *(uint4*)(smem+SMA+so) = *(const uint4*)(g_qhi + (size_t)m0*DIM + go);
            *(uint4*)(smem+SMB+so) = *(const uint4*)(g_shi + (size_t)n0*DIM + go);
        }
        __syncthreads();
        #pragma unroll
        for (int s=0;s<4;s++){
            int cc = s*2 + (g>>1);
            uint32_t a[4][4], bfr[4][2];
            #pragma unroll
            for (int mf=0;mf<4;mf++){
                int r = wm0 + mf*16 + (g&1)*8 + lr;
                LDSM4(a[mf][0],a[mf][1],a[mf][2],a[mf][3], sb + SMA + r*128 + ((cc ^ (r&7))<<4));
            }
            #pragma unroll
            for (int np=0;np<2;np++){
                int r = wn0 + np*16 + (g&1)*8 + lr;
                uint32_t t0,t1,t2,t3;
                LDSM4(t0,t1,t2,t3, sb + SMB + r*128 + ((cc ^ (r&7))<<4));
                bfr[np*2][0]=t0;   bfr[np*2][1]=t2;
                bfr[np*2+1][0]=t1; bfr[np*2+1][1]=t3;
            }
            #pragma unroll
            for (int mf=0;mf<4;mf++)
                #pragma unroll
                for (int nf=0;nf<4;nf++)
                    MMA16816(acc[mf][nf], a[mf], bfr[nf]);
        }
        __syncthreads();
    }
    int rbase = m0 + wm0 + (lane>>2);
    int cbase = n0 + wn0 + (lane&3)*2;
    #pragma unroll
    for (int mf=0;mf<4;mf++)
        #pragma unroll
        for (int h=0;h<2;h++){
            float qn = g_qn[rbase + mf*16 + h*8];
            #pragma unroll
            for (int nf=0;nf<4;nf++){
                int col = cbase + nf*8;
                float v0 = fmaxf(qn + g_sn[col]   - 2.f*acc[mf][nf][h*2+0], 0.f);
                float v1 = fmaxf(qn + g_sn[col+1] - 2.f*acc[mf][nf][h*2+1], 0.f);
                int b0=(int)(v0*2.0f); if(b0>SBIN-1)b0=SBIN-1;
                int b1=(int)(v1*2.0f); if(b1>SBIN-1)b1=SBIN-1;
                atomicAdd(&sh[b0],1u); atomicAdd(&sh[b1],1u);
            }
        }
    __syncthreads();
    for (int b=tid;b<SBIN;b+=256)
        if (sh[b]) atomicAdd(&g_h1[b], sh[b]);
}

extern "C" __global__ void k_gamma(){
    __shared__ unsigned long long ps[256];
    int tid = threadIdx.x;
    unsigned int loc[8];
    unsigned long long s = 0ull;
    #pragma unroll
    for (int t=0;t<8;t++){ loc[t] = g_h1[tid*8+t]; s += loc[t]; }
    ps[tid] = s; __syncthreads();
    for (int o=1;o<256;o<<=1){
        unsigned long long v = (tid>=o) ? ps[tid-o] : 0ull;
        __syncthreads();
        ps[tid] += v;
        __syncthreads();
    }
    unsigned long long before = ps[tid] - s;
    if (before < SKRANK && ps[tid] >= SKRANK){
        unsigned long long cum = before;
        #pragma unroll
        for (int t=0;t<8;t++){
            if (cum + loc[t] >= SKRANK){
                float frac = (float)(SKRANK - cum) / (float)(loc[t] ? loc[t] : 1u);
                float med = ((float)(tid*8+t) + frac) * 0.5f;
                g_gamma = 1.f/(med + 1e-6f);
                break;
            }
            cum += loc[t];
        }
    }
}

// ---- main d2 GEMM: cp.async double-buffered, fused softmax reduction -------
__device__ __forceinline__ void d2_issue_loads(uint32_t sbuf, int m0, int n0,
                                               int kc, int tid){
    #pragma unroll
    for (int p=0;p<4;p++){
        int idx = tid + p*256;
        int r = idx>>3, c = idx&7;
        size_t go = (size_t)r*DIM + kc*64 + c*8;
        uint32_t so = (uint32_t)(r*128 + ((c ^ (r&7))<<4));
        cp16(sbuf + so,         g_qhi + (size_t)m0*DIM + go);
        cp16(sbuf + 16384 + so, g_shi + (size_t)n0*DIM + go);
    }
}

extern "C" __global__ __launch_bounds__(256) void k_d2mma(const float* __restrict__ sv){
    extern __shared__ char smem[];
    uint32_t sb = smem_u32(smem);
    float* rAccW = (float*)(smem + SMX_M);
    float* rAccV = rAccW + 128;
    float* sv_s  = rAccV + 128;
    int tid = threadIdx.x, wid = tid>>5, lane = tid&31;
    int m0 = blockIdx.y*128, n0 = blockIdx.x*128;
    int wm0 = (wid&1)*64, wn0 = (wid>>1)*32;
    ((float*)(smem+SMX_M))[tid] = 0.f;       // zeroes rAccW+rAccV
    if (tid < 128) sv_s[tid] = sv[n0 + tid];
    float acc[4][4][4] = {};
    int g = lane>>3, lr = lane&7;

    d2_issue_loads(sb, m0, n0, 0, tid);
    CP_COMMIT();
    for (int kc=0;kc<4;kc++){
        uint32_t buf = sb + (uint32_t)((kc&1)*32768);
        if (kc < 3){
            d2_issue_loads(sb + (uint32_t)(((kc+1)&1)*32768), m0, n0, kc+1, tid);
            CP_COMMIT();
            CP_WAIT(1);
        } else {
            CP_WAIT(0);
        }
        __syncthreads();
        #pragma unroll
        for (int s=0;s<4;s++){
            int cc = s*2 + (g>>1);
            uint32_t a[4][4], bfr[4][2];
            #pragma unroll
            for (int mf=0;mf<4;mf++){
                int r = wm0 + mf*16 + (g&1)*8 + lr;
                LDSM4(a[mf][0],a[mf][1],a[mf][2],a[mf][3], buf + r*128 + ((cc ^ (r&7))<<4));
            }
            #pragma unroll
            for (int np=0;np<2;np++){
                int r = wn0 + np*16 + (g&1)*8 + lr;
                uint32_t t0,t1,t2,t3;
                LDSM4(t0,t1,t2,t3, buf + 16384 + r*128 + ((cc ^ (r&7))<<4));
                bfr[np*2][0]=t0;   bfr[np*2][1]=t2;
                bfr[np*2+1][0]=t1; bfr[np*2+1][1]=t3;
            }
            #pragma unroll
            for (int mf=0;mf<4;mf++)
                #pragma unroll
                for (int nf=0;nf<4;nf++)
                    MMA16816(acc[mf][nf], a[mf], bfr[nf]);
        }
        __syncthreads();
    }
    float gamma = g_gamma;
    int lr0 = wm0 + (lane>>2);
    int cb = wn0 + (lane&3)*2;
    #pragma unroll
    for (int mf=0;mf<4;mf++)
        #pragma unroll
        for (int h=0;h<2;h++){
            int lrow = lr0 + mf*16 + h*8;
            float qn = g_qn[m0 + lrow];
            float sw = 0.f, swv = 0.f;
            #pragma unroll
            for (int nf=0;nf<4;nf++){
                int col = cb + nf*8;
                float d0 = fmaxf(qn + g_sn[n0+col]   - 2.f*acc[mf][nf][h*2+0], 0.f);
                float d1 = fmaxf(qn + g_sn[n0+col+1] - 2.f*acc[mf][nf][h*2+1], 0.f);
                float w0 = __expf(-gamma*d0);
                float w1 = __expf(-gamma*d1);
                sw  += w0 + w1;
                swv += w0*sv_s[col] + w1*sv_s[col+1];
            }
            sw  += __shfl_xor_sync(0xffffffffu, sw, 1);
            swv += __shfl_xor_sync(0xffffffffu, swv, 1);
            sw  += __shfl_xor_sync(0xffffffffu, sw, 2);
            swv += __shfl_xor_sync(0xffffffffu, swv, 2);
            if ((lane&3)==0){
                atomicAdd(&rAccW[lrow], sw);
                atomicAdd(&rAccV[lrow], swv);
            }
        }
    __syncthreads();
    if (tid < 128){
        atomicAdd(&g_accw[m0+tid],  rAccW[tid]);
        atomicAdd(&g_accwv[m0+tid], rAccV[tid]);
    }
}

extern "C" __global__ void k_predfin(float* __restrict__ out){
    int q = blockIdx.x*blockDim.x + threadIdx.x;
    if (q < NQ) out[(size_t)NQ*NCLS + q] = g_accwv[q]/g_accw[q];
}

extern "C" void kernel_launch(void* const* d_in, const int* in_sizes, int n_in,
                              void* d_out, int out_size){
    const float* sf  = (const float*)d_in[0];
    const int*   lab = (const int*)  d_in[1];
    const float* sv  = (const float*)d_in[2];
    const float* qf  = (const float*)d_in[3];
    float* out = (float*)d_out;
    (void)in_sizes; (void)n_in; (void)out_size;

    cudaFuncSetAttribute(k_d2samp, cudaFuncAttributeMaxDynamicSharedMemorySize, SMT_S);
    cudaFuncSetAttribute(k_d2mma,  cudaFuncAttributeMaxDynamicSharedMemorySize, SMT_M);

    k_zero<<<256,256>>>();
    k_support<<<128,256>>>(sf, lab);
    k_covgemm<<<dim3(10,1,32),256>>>(sf);
    k_finalize<<<9,256>>>();
    k_logits<<<NQ/4,256>>>(qf, out);
    k_covA<<<64,256>>>();
    k_covB<<<64,256>>>();
    // NS iter 1 (algebraic): Y0 slot0, T0==Z1 slot1.  Y1 = Y0 @ T0 -> slot3
    k_mm256<<<dim3(8,8),256>>>(0, 1, 3, 1);
    // NS iters 2..3 (full): state Y slot3, Z slot1
    int py=3, pz=1, py2=0, pz2=4;
    for (int it=0; it<2; it++){
        k_mm256<<<dim3(8,8),256>>>(pz, py, 2, 0);
        k_mm256pair<<<dim3(8,8,2),256>>>(py, pz, py2, pz2);
        int t = py; py = py2; py2 = t;
        t = pz; pz = pz2; pz2 = t;
    }
    k_whiten<<<dim3(4,NSUP/128),256>>>(sf, pz, 0);
    k_whiten<<<dim3(4,NQ/128),256>>>(qf, pz, 1);
    k_d2samp<<<dim3(16,8),256,SMT_S>>>();
    k_gamma<<<1,256>>>();
    k_d2mma<<<dim3(NSUP/128,NQ/128),256,SMT_M>>>(sv);
    k_predfin<<<NQ/256,256>>>(out);
}

// round 15
// speedup vs baseline: 1.1517x; 1.0109x over previous
#include <cuda_runtime.h>
#include <cuda_bf16.h>
#include <math.h>
#include <stdint.h>

#define NSUP 16384
#define NQ   8192
#define DIM  256
#define NCLS 64
#define SBIN 2048
#define SKRANK 1048576ULL   /* (1024*2048)/2 */

__device__ float g_psum[NCLS*DIM];
__device__ float g_cnt[NCLS];
__device__ float g_protoT[DIM*NCLS];
__device__ float g_musum[DIM];
__device__ float g_mu[DIM];
__device__ float g_G[DIM*DIM];
__device__ float g_Y[DIM*DIM];
__device__ float g_Z[DIM*DIM];
__device__ float g_T[DIM*DIM];
__device__ float g_Y2[DIM*DIM];
__device__ float g_Z2[DIM*DIM];
__device__ float g_trsum;
__device__ float g_gamma;
__device__ __nv_bfloat16 g_shi[NSUP*DIM];
__device__ __nv_bfloat16 g_qhi[NQ*DIM];
__device__ float g_sn[NSUP];
__device__ float g_qn[NQ];
__device__ float g_accw[NQ];
__device__ float g_accwv[NQ];
__device__ unsigned int g_h1[SBIN];

__device__ __forceinline__ float warp_sum(float v){
    #pragma unroll
    for (int o = 16; o; o >>= 1) v += __shfl_xor_sync(0xffffffffu, v, o);
    return v;
}
__device__ __forceinline__ float warp_max(float v){
    #pragma unroll
    for (int o = 16; o; o >>= 1) v = fmaxf(v, __shfl_xor_sync(0xffffffffu, v, o));
    return v;
}
__device__ __forceinline__ float* bsel(int id){
    switch(id){ case 0: return g_Y; case 1: return g_Z; case 2: return g_T;
                case 3: return g_Y2; default: return g_Z2; }
}
__device__ __forceinline__ uint32_t smem_u32(const void* p){
    uint32_t a;
    asm("{ .reg .u64 t; cvta.to.shared.u64 t, %1; cvt.u32.u64 %0, t; }" : "=r"(a) : "l"(p));
    return a;
}
__device__ __forceinline__ void cp16(uint32_t saddr, const void* gptr){
    asm volatile("cp.async.cg.shared.global [%0], [%1], 16;" :: "r"(saddr), "l"(gptr));
}
#define CP_COMMIT() asm volatile("cp.async.commit_group;" ::: "memory")
#define CP_WAIT(n)  asm volatile("cp.async.wait_group %0;" :: "n"(n) : "memory")
#define LDSM4(r0,r1,r2,r3,addr) \
    asm volatile("ldmatrix.sync.aligned.m8n8.x4.shared.b16 {%0,%1,%2,%3}, [%4];" \
        : "=r"(r0),"=r"(r1),"=r"(r2),"=r"(r3) : "r"(addr))
#define MMA16816(c,a,b) \
    asm volatile("mma.sync.aligned.m16n8k16.row.col.f32.bf16.bf16.f32 " \
        "{%0,%1,%2,%3},{%4,%5,%6,%7},{%8,%9},{%0,%1,%2,%3};" \
        : "+f"((c)[0]),"+f"((c)[1]),"+f"((c)[2]),"+f"((c)[3]) \
        : "r"((a)[0]),"r"((a)[1]),"r"((a)[2]),"r"((a)[3]), "r"((b)[0]),"r"((b)[1]))
// packed fp32x2 fma (bit-exact pair of fma.rn.f32)
__device__ __forceinline__ void ffma2(unsigned long long &d,
                                      unsigned long long a,
                                      unsigned long long b){
    asm("fma.rn.f32x2 %0, %1, %2, %0;" : "+l"(d) : "l"(a), "l"(b));
}
__device__ __forceinline__ unsigned long long dup2(float x){
    unsigned long long r;
    asm("mov.b64 %0, {%1, %1};" : "=l"(r) : "f"(x));
    return r;
}
__device__ __forceinline__ float2 unpk(unsigned long long x){
    float2 f;
    f.x = __uint_as_float((unsigned int)x);
    f.y = __uint_as_float((unsigned int)(x >> 32));
    return f;
}

// ---------------------------------------------------------------------------
extern "C" __global__ void k_zero(){
    int i = blockIdx.x*blockDim.x + threadIdx.x, st = gridDim.x*blockDim.x;
    for (int e=i; e<NCLS*DIM; e+=st) g_psum[e]=0.f;
    for (int e=i; e<NCLS;     e+=st) g_cnt[e]=0.f;
    for (int e=i; e<DIM;      e+=st) g_musum[e]=0.f;
    for (int e=i; e<DIM*DIM;  e+=st) g_G[e]=0.f;
    for (int e=i; e<SBIN;     e+=st) g_h1[e]=0u;
    for (int e=i; e<NSUP;     e+=st) g_sn[e]=0.f;
    for (int e=i; e<NQ;       e+=st){ g_qn[e]=0.f; g_accw[e]=0.f; g_accwv[e]=0.f; }
    if (i==0) g_trsum = 0.f;
}

extern "C" __global__ __launch_bounds__(256) void k_support(
        const float* __restrict__ sf, const int* __restrict__ lab){
    int w = threadIdx.x>>5, lane = threadIdx.x&31;
    int r0 = blockIdx.x * (NSUP/gridDim.x);
    float msum[8];
    #pragma unroll
    for (int t=0;t<8;t++) msum[t]=0.f;
    for (int r = r0+w; r < r0 + NSUP/gridDim.x; r += 8){
        const float* row = sf + (size_t)r*DIM;
        float x[8], ss=0.f;
        #pragma unroll
        for (int t=0;t<8;t++){ x[t]=row[lane+32*t]; ss += x[t]*x[t]; }
        ss = warp_sum(ss);
        float inv = 1.f / fmaxf(sqrtf(ss), 1e-8f);
        int lb = lab[r];
        #pragma unroll
        for (int t=0;t<8;t++){
            msum[t] += x[t];
            atomicAdd(&g_psum[lb*DIM + lane + 32*t], x[t]*inv);
        }
        if (!lane) atomicAdd(&g_cnt[lb], 1.f);
    }
    #pragma unroll
    for (int t=0;t<8;t++) atomicAdd(&g_musum[lane+32*t], msum[t]);
}

extern "C" __global__ void k_finalize(){
    int tid = threadIdx.x, w = tid>>5, lane = tid&31;
    if (blockIdx.x == 0){
        if (tid < DIM) g_mu[tid] = g_musum[tid] * (1.f/NSUP);
        return;
    }
    int c = (blockIdx.x-1)*8 + w;
    float ic = 1.f / fmaxf(g_cnt[c], 1.f);
    float v[8], ss=0.f;
    #pragma unroll
    for (int t=0;t<8;t++){ v[t]=g_psum[c*DIM+lane+32*t]*ic; ss+=v[t]*v[t]; }
    ss = warp_sum(ss);
    float inv = 1.f / fmaxf(sqrtf(ss), 1e-8f);
    #pragma unroll
    for (int t=0;t<8;t++) g_protoT[(lane+32*t)*NCLS + c] = v[t]*inv;
}

extern "C" __global__ __launch_bounds__(256) void k_logits(
        const float* __restrict__ qf, float* __restrict__ out){
    __shared__ float sq[4][260];
    __shared__ float sred[8], sinv[4], smax[8], ssum[8];
    int tid = threadIdx.x, w = tid>>5, lane = tid&31;
    int q0 = blockIdx.x*4;
    #pragma unroll
    for (int p=0;p<4;p++) sq[p][tid] = qf[(size_t)(q0+p)*DIM + tid];
    __syncthreads();
    { int row = w>>1, base = (w&1)*128;
      float s=0.f;
      #pragma unroll
      for (int t=0;t<4;t++){ float v=sq[row][base+lane+32*t]; s+=v*v; }
      s = warp_sum(s);
      if (!lane) sred[w]=s; }
    __syncthreads();
    if (tid<4) sinv[tid] = 1.f / fmaxf(sqrtf(sred[2*tid]+sred[2*tid+1]), 1e-8f);
    __syncthreads();
    int c = tid&63, qi = tid>>6;
    float acc = 0.f;
    #pragma unroll 8
    for (int k=0;k<DIM;k++) acc = fmaf(sq[qi][k], g_protoT[k*NCLS+c], acc);
    acc *= sinv[qi];
    float m = warp_max(acc);
    if (!lane) smax[w]=m;
    __syncthreads();
    m = fmaxf(smax[qi*2], smax[qi*2+1]);
    float e = expf(acc - m);
    float s = warp_sum(e);
    if (!lane) ssum[w]=s;
    __syncthreads();
    float lse = m + logf(ssum[qi*2]+ssum[qi*2+1]);
    out[(size_t)(q0+qi)*NCLS + c] = acc - lse;
}

// symmetric: only upper-triangle 64x64 block pairs (10 of 16); f32x2 core
extern "C" __global__ __launch_bounds__(256) void k_covgemm(const float* __restrict__ X){
    const int pi[10] = {0,0,0,0,1,1,1,2,2,3};
    const int pj[10] = {0,1,2,3,1,2,3,2,3,3};
    __shared__ float Xa[16][68], Xb[16][68];
    int tid = threadIdx.x, tx = tid&15, ty = tid>>4;
    int i0 = pi[blockIdx.x]*64, j0 = pj[blockIdx.x]*64;
    int chunk = NSUP/gridDim.z, rb = blockIdx.z*chunk;
    unsigned long long acc2[4][2];
    #pragma unroll
    for (int u=0;u<4;u++){ acc2[u][0]=0ull; acc2[u][1]=0ull; }
    for (int r = rb; r < rb+chunk; r += 16){
        #pragma unroll
        for (int p=0;p<4;p++){
            int lin = tid + p*256, rr = lin>>6, c = lin&63;
            Xa[rr][c] = X[(size_t)(r+rr)*DIM + i0 + c];
            Xb[rr][c] = X[(size_t)(r+rr)*DIM + j0 + c];
        }
        __syncthreads();
        #pragma unroll
        for (int kk=0;kk<16;kk++){
            float4 a = *(const float4*)&Xa[kk][ty*4];
            ulonglong2 b = *(const ulonglong2*)&Xb[kk][tx*4];
            unsigned long long ad[4] = {dup2(a.x), dup2(a.y), dup2(a.z), dup2(a.w)};
            #pragma unroll
            for (int u=0;u<4;u++){
                ffma2(acc2[u][0], ad[u], b.x);
                ffma2(acc2[u][1], ad[u], b.y);
            }
        }
        __syncthreads();
    }
    #pragma unroll
    for (int u=0;u<4;u++){
        float2 p0 = unpk(acc2[u][0]), p1 = unpk(acc2[u][1]);
        float vv[4] = {p0.x, p0.y, p1.x, p1.y};
        #pragma unroll
        for (int v=0;v<4;v++)
            atomicAdd(&g_G[(i0+ty*4+u)*DIM + j0+tx*4+v], vv[v]);
    }
}

// mirror lower triangle from upper
extern "C" __global__ void k_covA(){
    __shared__ float red[256];
    int tid = threadIdx.x;
    float tr = 0.f;
    #pragma unroll
    for (int p=0;p<4;p++){
        int e = blockIdx.x*1024 + p*256 + tid;
        int i = e>>8, j = e&255;
        int src = (i<=j) ? e : (j*DIM + i);
        float v = (g_G[src] - (float)NSUP*g_mu[i]*g_mu[j]) * (1.f/(NSUP-1));
        if (i==j){ v += 1e-4f; tr += v; }
        g_T[e] = v;
    }
    red[tid]=tr; __syncthreads();
    for (int s=128;s;s>>=1){ if(tid<s) red[tid]+=red[tid+s]; __syncthreads(); }
    if (!tid && red[0] != 0.f) atomicAdd(&g_trsum, red[0]);
}

// normalize + init: Y0 = Anorm, Z slot <- T0 = 1.5I - 0.5*Y0 (algebraic NS iter 1)
extern "C" __global__ void k_covB(){
    float ic = (float)DIM / g_trsum;
    int tid = threadIdx.x;
    #pragma unroll
    for (int p=0;p<4;p++){
        int e = blockIdx.x*1024 + p*256 + tid;
        int i = e>>8, j = e&255;
        float y0 = g_T[e]*ic;
        g_Y[e] = y0;
        g_Z[e] = ((i==j)?1.5f:0.f) - 0.5f*y0;   // T0 == Z1
    }
}

extern "C" __global__ __launch_bounds__(256) void k_mm256(int ia,int ib,int ic,int mode){
    const float* A = bsel(ia); const float* B = bsel(ib); float* C = bsel(ic);
    __shared__ float As[32][33], Bs[32][33];
    int tid = threadIdx.x, tx = tid&15, ty = tid>>4;
    int j0 = blockIdx.x*32, i0 = blockIdx.y*32;
    float a00=0,a01=0,a10=0,a11=0;
    for (int k0=0;k0<DIM;k0+=32){
        #pragma unroll
        for (int p=0;p<4;p++){
            int lin = tid+p*256, r = lin>>5, c = lin&31;
            As[r][c] = A[(i0+r)*DIM + k0+c];
            Bs[r][c] = B[(k0+r)*DIM + j0+c];
        }
        __syncthreads();
        #pragma unroll
        for (int kk=0;kk<32;kk++){
            float x0=As[ty*2][kk], x1=As[ty*2+1][kk];
            float y0=Bs[kk][tx*2], y1=Bs[kk][tx*2+1];
            a00=fmaf(x0,y0,a00); a01=fmaf(x0,y1,a01);
            a10=fmaf(x1,y0,a10); a11=fmaf(x1,y1,a11);
        }
        __syncthreads();
    }
    int i = i0+ty*2, j = j0+tx*2;
    float o[2][2] = {{a00,a01},{a10,a11}};
    #pragma unroll
    for (int u=0;u<2;u++)
        #pragma unroll
        for (int v=0;v<2;v++){
            float val = o[u][v];
            if (mode==0) val = ((i+u==j+v)?1.5f:0.f) - 0.5f*val;
            C[(i+u)*DIM + j+v] = val;
        }
}

extern "C" __global__ __launch_bounds__(256) void k_mm256pair(int py,int pz,int py2,int pz2){
    const float* A; const float* B; float* C;
    if (blockIdx.z == 0){ A = bsel(py); B = g_T; C = bsel(py2); }
    else                { A = g_T; B = bsel(pz); C = bsel(pz2); }
    __shared__ float As[32][33], Bs[32][33];
    int tid = threadIdx.x, tx = tid&15, ty = tid>>4;
    int j0 = blockIdx.x*32, i0 = blockIdx.y*32;
    float a00=0,a01=0,a10=0,a11=0;
    for (int k0=0;k0<DIM;k0+=32){
        #pragma unroll
        for (int p=0;p<4;p++){
            int lin = tid+p*256, r = lin>>5, c = lin&31;
            As[r][c] = A[(i0+r)*DIM + k0+c];
            Bs[r][c] = B[(k0+r)*DIM + j0+c];
        }
        __syncthreads();
        #pragma unroll
        for (int kk=0;kk<32;kk++){
            float x0=As[ty*2][kk], x1=As[ty*2+1][kk];
            float y0=Bs[kk][tx*2], y1=Bs[kk][tx*2+1];
            a00=fmaf(x0,y0,a00); a01=fmaf(x0,y1,a01);
            a10=fmaf(x1,y0,a10); a11=fmaf(x1,y1,a11);
        }
        __syncthreads();
    }
    int i = i0+ty*2, j = j0+tx*2;
    C[i*DIM + j]       = a00;
    C[i*DIM + j+1]     = a01;
    C[(i+1)*DIM + j]   = a10;
    C[(i+1)*DIM + j+1] = a11;
}

// whiten + fused muZ + fused bf16 convert + fused row-norm partials; f32x2 core
extern "C" __global__ __launch_bounds__(256) void k_whiten(
        const float* __restrict__ Xin, int zid, int wsel){
    const float* M = bsel(zid);
    __nv_bfloat16* Bout = wsel ? g_qhi : g_shi;
    float* Nout = wsel ? g_qn : g_sn;
    __shared__ float Xs[16][132], Ms[16][68];
    __shared__ float muzp[4][64];
    __shared__ float muz[64];
    int tid = threadIdx.x, tx = tid&15, ty = tid>>4;
    int m0 = blockIdx.y*128, j0 = blockIdx.x*64;
    { int col = tid>>2, part = tid&3;
      float s = 0.f;
      #pragma unroll 16
      for (int k=part*64; k<part*64+64; k++) s = fmaf(g_mu[k], M[k*DIM + j0 + col], s);
      muzp[part][col] = s; }
    __syncthreads();
    if (tid < 64) muz[tid] = muzp[0][tid]+muzp[1][tid]+muzp[2][tid]+muzp[3][tid];
    unsigned long long acc2[8][2];
    #pragma unroll
    for (int u=0;u<8;u++){ acc2[u][0]=0ull; acc2[u][1]=0ull; }
    for (int k0=0;k0<DIM;k0+=16){
        #pragma unroll
        for (int p=0;p<2;p++){
            int lin = tid+p*256, m = lin>>2, c4 = (lin&3)*4;
            float4 v = *(const float4*)(Xin + (size_t)(m0+m)*DIM + k0 + c4);
            Xs[c4][m]=v.x; Xs[c4+1][m]=v.y; Xs[c4+2][m]=v.z; Xs[c4+3][m]=v.w;
        }
        { int r = tid>>4, c4 = (tid&15)*4;
          *(float4*)&Ms[r][c4] = *(const float4*)(M + (k0+r)*DIM + j0 + c4); }
        __syncthreads();
        #pragma unroll
        for (int kk=0;kk<16;kk++){
            float4 a0 = *(const float4*)&Xs[kk][ty*8];
            float4 a1 = *(const float4*)&Xs[kk][ty*8+4];
            ulonglong2 b = *(const ulonglong2*)&Ms[kk][tx*4];
            unsigned long long ad[8] = {dup2(a0.x), dup2(a0.y), dup2(a0.z), dup2(a0.w),
                                        dup2(a1.x), dup2(a1.y), dup2(a1.z), dup2(a1.w)};
            #pragma unroll
            for (int u=0;u<8;u++){
                ffma2(acc2[u][0], ad[u], b.x);
                ffma2(acc2[u][1], ad[u], b.y);
            }
        }
        __syncthreads();
    }
    float rs = sqrtf((float)DIM / g_trsum);
    float mz[4];
    #pragma unroll
    for (int v=0;v<4;v++) mz[v] = muz[tx*4+v];
    #pragma unroll
    for (int u=0;u<8;u++){
        float2 p0 = unpk(acc2[u][0]), p1 = unpk(acc2[u][1]);
        float av[4] = {p0.x, p0.y, p1.x, p1.y};
        float vv[4]; float ss = 0.f;
        #pragma unroll
        for (int v=0;v<4;v++){ vv[v]=(av[v]-mz[v])*rs; ss += vv[v]*vv[v]; }
        __nv_bfloat16 h[4];
        #pragma unroll
        for (int v=0;v<4;v++) h[v] = __float2bfloat16_rn(vv[v]);
        int row = m0 + ty*8 + u;
        *(ushort4*)(Bout + (size_t)row*DIM + j0 + tx*4) =
            make_ushort4(*(unsigned short*)&h[0], *(unsigned short*)&h[1],
                         *(unsigned short*)&h[2], *(unsigned short*)&h[3]);
        atomicAdd(&Nout[row], ss);
    }
}

// ---- sample d2 GEMM for gamma ---------------------------------------------
#define SMA   0
#define SMB   16384
#define SMX_S 32768
#define SMT_S 40960
#define SMX_M 65536
#define SMT_M 67072

extern "C" __global__ __launch_bounds__(256) void k_d2samp(){
    extern __shared__ char smem[];
    uint32_t sb = smem_u32(smem);
    unsigned int* sh = (unsigned int*)(smem + SMX_S);
    int tid = threadIdx.x, wid = tid>>5, lane = tid&31;
    int m0 = blockIdx.y*128, n0 = blockIdx.x*128;
    int wm0 = (wid&1)*64, wn0 = (wid>>1)*32;
    for (int b=tid;b<SBIN;b+=256) sh[b]=0u;
    float acc[4][4][4] = {};
    int g = lane>>3, lr = lane&7;
    for (int kc=0;kc<4;kc++){
        #pragma unroll
        for (int p=0;p<4;p++){
            int idx = tid + p*256;
            int r = idx>>3, c = idx&7;
            size_t go = (size_t)r*DIM + kc*64 + c*8;
            uint32_t so = (uint32_t)(r*128 + ((c ^ (r&7))<<4));
            *(uint4*)(smem+SMA+so) = *(const uint4*)(g_qhi + (size_t)m0*DIM + go);
            *(uint4*)(smem+SMB+so) = *(const uint4*)(g_shi + (size_t)n0*DIM + go);
        }
        __syncthreads();
        #pragma unroll
        for (int s=0;s<4;s++){
            int cc = s*2 + (g>>1);
            uint32_t a[4][4], bfr[4][2];
            #pragma unroll
            for (int mf=0;mf<4;mf++){
                int r = wm0 + mf*16 + (g&1)*8 + lr;
                LDSM4(a[mf][0],a[mf][1],a[mf][2],a[mf][3], sb + SMA + r*128 + ((cc ^ (r&7))<<4));
            }
            #pragma unroll
            for (int np=0;np<2;np++){
                int r = wn0 + np*16 + (g&1)*8 + lr;
                uint32_t t0,t1,t2,t3;
                LDSM4(t0,t1,t2,t3, sb + SMB + r*128 + ((cc ^ (r&7))<<4));
                bfr[np*2][0]=t0;   bfr[np*2][1]=t2;
                bfr[np*2+1][0]=t1; bfr[np*2+1][1]=t3;
            }
            #pragma unroll
            for (int mf=0;mf<4;mf++)
                #pragma unroll
                for (int nf=0;nf<4;nf++)
                    MMA16816(acc[mf][nf], a[mf], bfr[nf]);
        }
        __syncthreads();
    }
    int rbase = m0 + wm0 + (lane>>2);
    int cbase = n0 + wn0 + (lane&3)*2;
    #pragma unroll
    for (int mf=0;mf<4;mf++)
        #pragma unroll
        for (int h=0;h<2;h++){
            float qn = g_qn[rbase + mf*16 + h*8];
            #pragma unroll
            for (int nf=0;nf<4;nf++){
                int col = cbase + nf*8;
                float v0 = fmaxf(qn + g_sn[col]   - 2.f*acc[mf][nf][h*2+0], 0.f);
                float v1 = fmaxf(qn + g_sn[col+1] - 2.f*acc[mf][nf][h*2+1], 0.f);
                int b0=(int)(v0*2.0f); if(b0>SBIN-1)b0=SBIN-1;
                int b1=(int)(v1*2.0f); if(b1>SBIN-1)b1=SBIN-1;
                atomicAdd(&sh[b0],1u); atomicAdd(&sh[b1],1u);
            }
        }
    __syncthreads();
    for (int b=tid;b<SBIN;b+=256)
        if (sh[b]) atomicAdd(&g_h1[b], sh[b]);
}

extern "C" __global__ void k_gamma(){
    __shared__ unsigned long long ps[256];
    int tid = threadIdx.x;
    unsigned int loc[8];
    unsigned long long s = 0ull;
    #pragma unroll
    for (int t=0;t<8;t++){ loc[t] = g_h1[tid*8+t]; s += loc[t]; }
    ps[tid] = s; __syncthreads();
    for (int o=1;o<256;o<<=1){
        unsigned long long v = (tid>=o) ? ps[tid-o] : 0ull;
        __syncthreads();
        ps[tid] += v;
        __syncthreads();
    }
    unsigned long long before = ps[tid] - s;
    if (before < SKRANK && ps[tid] >= SKRANK){
        unsigned long long cum = before;
        #pragma unroll
        for (int t=0;t<8;t++){
            if (cum + loc[t] >= SKRANK){
                float frac = (float)(SKRANK - cum) / (float)(loc[t] ? loc[t] : 1u);
                float med = ((float)(tid*8+t) + frac) * 0.5f;
                g_gamma = 1.f/(med + 1e-6f);
                break;
            }
            cum += loc[t];
        }
    }
}

// ---- main d2 GEMM: cp.async double-buffered, fused softmax reduction -------
__device__ __forceinline__ void d2_issue_loads(uint32_t sbuf, int m0, int n0,
                                               int kc, int tid){
    #pragma unroll
    for (int p=0;p<4;p++){
        int idx = tid + p*256;
        int r = idx>>3, c = idx&7;
        size_t go = (size_t)r*DIM + kc*64 + c*8;
        uint32_t so = (uint32_t)(r*128 + ((c ^ (r&7))<<4));
        cp16(sbuf + so,         g_qhi + (size_t)m0*DIM + go);
        cp16(sbuf + 16384 + so, g_shi + (size_t)n0*DIM + go);
    }
}

extern "C" __global__ __launch_bounds__(256) void k_d2mma(const float* __restrict__ sv){
    extern __shared__ char smem[];
    uint32_t sb = smem_u32(smem);
    float* rAccW = (float*)(smem + SMX_M);
    float* rAccV = rAccW + 128;
    float* sv_s  = rAccV + 128;
    int tid = threadIdx.x, wid = tid>>5, lane = tid&31;
    int m0 = blockIdx.y*128, n0 = blockIdx.x*128;
    int wm0 = (wid&1)*64, wn0 = (wid>>1)*32;
    ((float*)(smem+SMX_M))[tid] = 0.f;       // zeroes rAccW+rAccV
    if (tid < 128) sv_s[tid] = sv[n0 + tid];
    float acc[4][4][4] = {};
    int g = lane>>3, lr = lane&7;

    d2_issue_loads(sb, m0, n0, 0, tid);
    CP_COMMIT();
    for (int kc=0;kc<4;kc++){
        uint32_t buf = sb + (uint32_t)((kc&1)*32768);
        if (kc < 3){
            d2_issue_loads(sb + (uint32_t)(((kc+1)&1)*32768), m0, n0, kc+1, tid);
            CP_COMMIT();
            CP_WAIT(1);
        } else {
            CP_WAIT(0);
        }
        __syncthreads();
        #pragma unroll
        for (int s=0;s<4;s++){
            int cc = s*2 + (g>>1);
            uint32_t a[4][4], bfr[4][2];
            #pragma unroll
            for (int mf=0;mf<4;mf++){
                int r = wm0 + mf*16 + (g&1)*8 + lr;
                LDSM4(a[mf][0],a[mf][1],a[mf][2],a[mf][3], buf + r*128 + ((cc ^ (r&7))<<4));
            }
            #pragma unroll
            for (int np=0;np<2;np++){
                int r = wn0 + np*16 + (g&1)*8 + lr;
                uint32_t t0,t1,t2,t3;
                LDSM4(t0,t1,t2,t3, buf + 16384 + r*128 + ((cc ^ (r&7))<<4));
                bfr[np*2][0]=t0;   bfr[np*2][1]=t2;
                bfr[np*2+1][0]=t1; bfr[np*2+1][1]=t3;
            }
            #pragma unroll
            for (int mf=0;mf<4;mf++)
                #pragma unroll
                for (int nf=0;nf<4;nf++)
                    MMA16816(acc[mf][nf], a[mf], bfr[nf]);
        }
        __syncthreads();
    }
    float gamma = g_gamma;
    int lr0 = wm0 + (lane>>2);
    int cb = wn0 + (lane&3)*2;
    #pragma unroll
    for (int mf=0;mf<4;mf++)
        #pragma unroll
        for (int h=0;h<2;h++){
            int lrow = lr0 + mf*16 + h*8;
            float qn = g_qn[m0 + lrow];
            float sw = 0.f, swv = 0.f;
            #pragma unroll
            for (int nf=0;nf<4;nf++){
                int col = cb + nf*8;
                float d0 = fmaxf(qn + g_sn[n0+col]   - 2.f*acc[mf][nf][h*2+0], 0.f);
                float d1 = fmaxf(qn + g_sn[n0+col+1] - 2.f*acc[mf][nf][h*2+1], 0.f);
                float w0 = __expf(-gamma*d0);
                float w1 = __expf(-gamma*d1);
                sw  += w0 + w1;
                swv += w0*sv_s[col] + w1*sv_s[col+1];
            }
            sw  += __shfl_xor_sync(0xffffffffu, sw, 1);
            swv += __shfl_xor_sync(0xffffffffu, swv, 1);
            sw  += __shfl_xor_sync(0xffffffffu, sw, 2);
            swv += __shfl_xor_sync(0xffffffffu, swv, 2);
            if ((lane&3)==0){
                atomicAdd(&rAccW[lrow], sw);
                atomicAdd(&rAccV[lrow], swv);
            }
        }
    __syncthreads();
    if (tid < 128){
        atomicAdd(&g_accw[m0+tid],  rAccW[tid]);
        atomicAdd(&g_accwv[m0+tid], rAccV[tid]);
    }
}

extern "C" __global__ void k_predfin(float* __restrict__ out){
    int q = blockIdx.x*blockDim.x + threadIdx.x;
    if (q < NQ) out[(size_t)NQ*NCLS + q] = g_accwv[q]/g_accw[q];
}

extern "C" void kernel_launch(void* const* d_in, const int* in_sizes, int n_in,
                              void* d_out, int out_size){
    const float* sf  = (const float*)d_in[0];
    const int*   lab = (const int*)  d_in[1];
    const float* sv  = (const float*)d_in[2];
    const float* qf  = (const float*)d_in[3];
    float* out = (float*)d_out;
    (void)in_sizes; (void)n_in; (void)out_size;

    cudaFuncSetAttribute(k_d2samp, cudaFuncAttributeMaxDynamicSharedMemorySize, SMT_S);
    cudaFuncSetAttribute(k_d2mma,  cudaFuncAttributeMaxDynamicSharedMemorySize, SMT_M);

    k_zero<<<256,256>>>();
    k_support<<<128,256>>>(sf, lab);
    k_covgemm<<<dim3(10,1,32),256>>>(sf);
    k_finalize<<<9,256>>>();
    k_logits<<<NQ/4,256>>>(qf, out);
    k_covA<<<64,256>>>();
    k_covB<<<64,256>>>();
    // NS iter 1 (algebraic): Y0 slot0, T0==Z1 slot1.  Y1 = Y0 @ T0 -> slot3
    k_mm256<<<dim3(8,8),256>>>(0, 1, 3, 1);
    // NS iters 2..3 (full): state Y slot3, Z slot1
    int py=3, pz=1, py2=0, pz2=4;
    for (int it=0; it<2; it++){
        k_mm256<<<dim3(8,8),256>>>(pz, py, 2, 0);
        k_mm256pair<<<dim3(8,8,2),256>>>(py, pz, py2, pz2);
        int t = py; py = py2; py2 = t;
        t = pz; pz = pz2; pz2 = t;
    }
    k_whiten<<<dim3(4,NSUP/128),256>>>(sf, pz, 0);
    k_whiten<<<dim3(4,NQ/128),256>>>(qf, pz, 1);
    k_d2samp<<<dim3(16,8),256,SMT_S>>>();
    k_gamma<<<1,256>>>();
    k_d2mma<<<dim3(NSUP/128,NQ/128),256,SMT_M>>>(sv);
    k_predfin<<<NQ/256,256>>>(out);
}

// round 16
// speedup vs baseline: 1.2320x; 1.0698x over previous
#include <cuda_runtime.h>
#include <cuda_bf16.h>
#include <math.h>
#include <stdint.h>

#define NSUP 16384
#define NQ   8192
#define DIM  256
#define NCLS 64
#define SBIN 2048
#define SKRANK 1048576ULL   /* (1024*2048)/2 */

__device__ float g_psum[NCLS*DIM];
__device__ float g_cnt[NCLS];
__device__ float g_protoT[DIM*NCLS];
__device__ float g_musum[DIM];
__device__ float g_mu[DIM];
__device__ float g_G[DIM*DIM];
__device__ float g_Y[DIM*DIM];
__device__ float g_Z[DIM*DIM];
__device__ float g_T[DIM*DIM];
__device__ float g_Y2[DIM*DIM];
__device__ float g_Z2[DIM*DIM];
__device__ float g_trsum;
__device__ float g_gamma;
__device__ __nv_bfloat16 g_shi[NSUP*DIM];
__device__ __nv_bfloat16 g_qhi[NQ*DIM];
__device__ float g_sn[NSUP];
__device__ float g_qn[NQ];
__device__ float g_accw[NQ];
__device__ float g_accwv[NQ];
__device__ unsigned int g_h1[SBIN];

__device__ __forceinline__ float warp_sum(float v){
    #pragma unroll
    for (int o = 16; o; o >>= 1) v += __shfl_xor_sync(0xffffffffu, v, o);
    return v;
}
__device__ __forceinline__ float warp_max(float v){
    #pragma unroll
    for (int o = 16; o; o >>= 1) v = fmaxf(v, __shfl_xor_sync(0xffffffffu, v, o));
    return v;
}
__device__ __forceinline__ float* bsel(int id){
    switch(id){ case 0: return g_Y; case 1: return g_Z; case 2: return g_T;
                case 3: return g_Y2; default: return g_Z2; }
}
__device__ __forceinline__ uint32_t smem_u32(const void* p){
    uint32_t a;
    asm("{ .reg .u64 t; cvta.to.shared.u64 t, %1; cvt.u32.u64 %0, t; }" : "=r"(a) : "l"(p));
    return a;
}
__device__ __forceinline__ void cp16(uint32_t saddr, const void* gptr){
    asm volatile("cp.async.cg.shared.global [%0], [%1], 16;" :: "r"(saddr), "l"(gptr));
}
#define CP_COMMIT() asm volatile("cp.async.commit_group;" ::: "memory")
#define CP_WAIT(n)  asm volatile("cp.async.wait_group %0;" :: "n"(n) : "memory")
#define LDSM4(r0,r1,r2,r3,addr) \
    asm volatile("ldmatrix.sync.aligned.m8n8.x4.shared.b16 {%0,%1,%2,%3}, [%4];" \
        : "=r"(r0),"=r"(r1),"=r"(r2),"=r"(r3) : "r"(addr))
#define MMA16816(c,a,b) \
    asm volatile("mma.sync.aligned.m16n8k16.row.col.f32.bf16.bf16.f32 " \
        "{%0,%1,%2,%3},{%4,%5,%6,%7},{%8,%9},{%0,%1,%2,%3};" \
        : "+f"((c)[0]),"+f"((c)[1]),"+f"((c)[2]),"+f"((c)[3]) \
        : "r"((a)[0]),"r"((a)[1]),"r"((a)[2]),"r"((a)[3]), "r"((b)[0]),"r"((b)[1]))
__device__ __forceinline__ void ffma2(unsigned long long &d,
                                      unsigned long long a,
                                      unsigned long long b){
    asm("fma.rn.f32x2 %0, %1, %2, %0;" : "+l"(d) : "l"(a), "l"(b));
}
__device__ __forceinline__ unsigned long long dup2(float x){
    unsigned long long r;
    asm("mov.b64 %0, {%1, %1};" : "=l"(r) : "f"(x));
    return r;
}
__device__ __forceinline__ float2 unpk(unsigned long long x){
    float2 f;
    f.x = __uint_as_float((unsigned int)x);
    f.y = __uint_as_float((unsigned int)(x >> 32));
    return f;
}

// ---------------------------------------------------------------------------
extern "C" __global__ void k_zero(){
    int i = blockIdx.x*blockDim.x + threadIdx.x, st = gridDim.x*blockDim.x;
    for (int e=i; e<NCLS*DIM; e+=st) g_psum[e]=0.f;
    for (int e=i; e<NCLS;     e+=st) g_cnt[e]=0.f;
    for (int e=i; e<DIM;      e+=st) g_musum[e]=0.f;
    for (int e=i; e<DIM*DIM;  e+=st) g_G[e]=0.f;
    for (int e=i; e<SBIN;     e+=st) g_h1[e]=0u;
    for (int e=i; e<NSUP;     e+=st) g_sn[e]=0.f;
    for (int e=i; e<NQ;       e+=st){ g_qn[e]=0.f; g_accw[e]=0.f; g_accwv[e]=0.f; }
    if (i==0) g_trsum = 0.f;
}

extern "C" __global__ __launch_bounds__(256) void k_support(
        const float* __restrict__ sf, const int* __restrict__ lab){
    int w = threadIdx.x>>5, lane = threadIdx.x&31;
    int r0 = blockIdx.x * (NSUP/gridDim.x);
    float msum[8];
    #pragma unroll
    for (int t=0;t<8;t++) msum[t]=0.f;
    for (int r = r0+w; r < r0 + NSUP/gridDim.x; r += 8){
        const float* row = sf + (size_t)r*DIM;
        float x[8], ss=0.f;
        #pragma unroll
        for (int t=0;t<8;t++){ x[t]=row[lane+32*t]; ss += x[t]*x[t]; }
        ss = warp_sum(ss);
        float inv = 1.f / fmaxf(sqrtf(ss), 1e-8f);
        int lb = lab[r];
        #pragma unroll
        for (int t=0;t<8;t++){
            msum[t] += x[t];
            atomicAdd(&g_psum[lb*DIM + lane + 32*t], x[t]*inv);
        }
        if (!lane) atomicAdd(&g_cnt[lb], 1.f);
    }
    #pragma unroll
    for (int t=0;t<8;t++) atomicAdd(&g_musum[lane+32*t], msum[t]);
}

extern "C" __global__ void k_finalize(){
    int tid = threadIdx.x, w = tid>>5, lane = tid&31;
    if (blockIdx.x == 0){
        if (tid < DIM) g_mu[tid] = g_musum[tid] * (1.f/NSUP);
        return;
    }
    int c = (blockIdx.x-1)*8 + w;
    float ic = 1.f / fmaxf(g_cnt[c], 1.f);
    float v[8], ss=0.f;
    #pragma unroll
    for (int t=0;t<8;t++){ v[t]=g_psum[c*DIM+lane+32*t]*ic; ss+=v[t]*v[t]; }
    ss = warp_sum(ss);
    float inv = 1.f / fmaxf(sqrtf(ss), 1e-8f);
    #pragma unroll
    for (int t=0;t<8;t++) g_protoT[(lane+32*t)*NCLS + c] = v[t]*inv;
}

extern "C" __global__ __launch_bounds__(256) void k_logits(
        const float* __restrict__ qf, float* __restrict__ out){
    __shared__ float sq[4][260];
    __shared__ float sred[8], sinv[4], smax[8], ssum[8];
    int tid = threadIdx.x, w = tid>>5, lane = tid&31;
    int q0 = blockIdx.x*4;
    #pragma unroll
    for (int p=0;p<4;p++) sq[p][tid] = qf[(size_t)(q0+p)*DIM + tid];
    __syncthreads();
    { int row = w>>1, base = (w&1)*128;
      float s=0.f;
      #pragma unroll
      for (int t=0;t<4;t++){ float v=sq[row][base+lane+32*t]; s+=v*v; }
      s = warp_sum(s);
      if (!lane) sred[w]=s; }
    __syncthreads();
    if (tid<4) sinv[tid] = 1.f / fmaxf(sqrtf(sred[2*tid]+sred[2*tid+1]), 1e-8f);
    __syncthreads();
    int c = tid&63, qi = tid>>6;
    float acc = 0.f;
    #pragma unroll 8
    for (int k=0;k<DIM;k++) acc = fmaf(sq[qi][k], g_protoT[k*NCLS+c], acc);
    acc *= sinv[qi];
    float m = warp_max(acc);
    if (!lane) smax[w]=m;
    __syncthreads();
    m = fmaxf(smax[qi*2], smax[qi*2+1]);
    float e = expf(acc - m);
    float s = warp_sum(e);
    if (!lane) ssum[w]=s;
    __syncthreads();
    float lse = m + logf(ssum[qi*2]+ssum[qi*2+1]);
    out[(size_t)(q0+qi)*NCLS + c] = acc - lse;
}

// symmetric: only upper-triangle 64x64 block pairs (10 of 16); f32x2 core
extern "C" __global__ __launch_bounds__(256) void k_covgemm(const float* __restrict__ X){
    const int pi[10] = {0,0,0,0,1,1,1,2,2,3};
    const int pj[10] = {0,1,2,3,1,2,3,2,3,3};
    __shared__ float Xa[16][68], Xb[16][68];
    int tid = threadIdx.x, tx = tid&15, ty = tid>>4;
    int i0 = pi[blockIdx.x]*64, j0 = pj[blockIdx.x]*64;
    int chunk = NSUP/gridDim.z, rb = blockIdx.z*chunk;
    unsigned long long acc2[4][2];
    #pragma unroll
    for (int u=0;u<4;u++){ acc2[u][0]=0ull; acc2[u][1]=0ull; }
    for (int r = rb; r < rb+chunk; r += 16){
        #pragma unroll
        for (int p=0;p<4;p++){
            int lin = tid + p*256, rr = lin>>6, c = lin&63;
            Xa[rr][c] = X[(size_t)(r+rr)*DIM + i0 + c];
            Xb[rr][c] = X[(size_t)(r+rr)*DIM + j0 + c];
        }
        __syncthreads();
        #pragma unroll
        for (int kk=0;kk<16;kk++){
            float4 a = *(const float4*)&Xa[kk][ty*4];
            ulonglong2 b = *(const ulonglong2*)&Xb[kk][tx*4];
            unsigned long long ad[4] = {dup2(a.x), dup2(a.y), dup2(a.z), dup2(a.w)};
            #pragma unroll
            for (int u=0;u<4;u++){
                ffma2(acc2[u][0], ad[u], b.x);
                ffma2(acc2[u][1], ad[u], b.y);
            }
        }
        __syncthreads();
    }
    #pragma unroll
    for (int u=0;u<4;u++){
        float2 p0 = unpk(acc2[u][0]), p1 = unpk(acc2[u][1]);
        float vv[4] = {p0.x, p0.y, p1.x, p1.y};
        #pragma unroll
        for (int v=0;v<4;v++)
            atomicAdd(&g_G[(i0+ty*4+u)*DIM + j0+tx*4+v], vv[v]);
    }
}

extern "C" __global__ void k_covA(){
    __shared__ float red[256];
    int tid = threadIdx.x;
    float tr = 0.f;
    #pragma unroll
    for (int p=0;p<4;p++){
        int e = blockIdx.x*1024 + p*256 + tid;
        int i = e>>8, j = e&255;
        int src = (i<=j) ? e : (j*DIM + i);
        float v = (g_G[src] - (float)NSUP*g_mu[i]*g_mu[j]) * (1.f/(NSUP-1));
        if (i==j){ v += 1e-4f; tr += v; }
        g_T[e] = v;
    }
    red[tid]=tr; __syncthreads();
    for (int s=128;s;s>>=1){ if(tid<s) red[tid]+=red[tid+s]; __syncthreads(); }
    if (!tid && red[0] != 0.f) atomicAdd(&g_trsum, red[0]);
}

extern "C" __global__ void k_covB(){
    float ic = (float)DIM / g_trsum;
    int tid = threadIdx.x;
    #pragma unroll
    for (int p=0;p<4;p++){
        int e = blockIdx.x*1024 + p*256 + tid;
        int i = e>>8, j = e&255;
        float y0 = g_T[e]*ic;
        g_Y[e] = y0;
        g_Z[e] = ((i==j)?1.5f:0.f) - 0.5f*y0;   // T0 == Z1
    }
}

extern "C" __global__ __launch_bounds__(256) void k_mm256(int ia,int ib,int ic,int mode){
    const float* A = bsel(ia); const float* B = bsel(ib); float* C = bsel(ic);
    __shared__ float As[32][33], Bs[32][33];
    int tid = threadIdx.x, tx = tid&15, ty = tid>>4;
    int j0 = blockIdx.x*32, i0 = blockIdx.y*32;
    float a00=0,a01=0,a10=0,a11=0;
    for (int k0=0;k0<DIM;k0+=32){
        #pragma unroll
        for (int p=0;p<4;p++){
            int lin = tid+p*256, r = lin>>5, c = lin&31;
            As[r][c] = A[(i0+r)*DIM + k0+c];
            Bs[r][c] = B[(k0+r)*DIM + j0+c];
        }
        __syncthreads();
        #pragma unroll
        for (int kk=0;kk<32;kk++){
            float x0=As[ty*2][kk], x1=As[ty*2+1][kk];
            float y0=Bs[kk][tx*2], y1=Bs[kk][tx*2+1];
            a00=fmaf(x0,y0,a00); a01=fmaf(x0,y1,a01);
            a10=fmaf(x1,y0,a10); a11=fmaf(x1,y1,a11);
        }
        __syncthreads();
    }
    int i = i0+ty*2, j = j0+tx*2;
    float o[2][2] = {{a00,a01},{a10,a11}};
    #pragma unroll
    for (int u=0;u<2;u++)
        #pragma unroll
        for (int v=0;v<2;v++){
            float val = o[u][v];
            if (mode==0) val = ((i+u==j+v)?1.5f:0.f) - 0.5f*val;
            C[(i+u)*DIM + j+v] = val;
        }
}

extern "C" __global__ __launch_bounds__(256) void k_mm256pair(int py,int pz,int py2,int pz2){
    const float* A; const float* B; float* C;
    if (blockIdx.z == 0){ A = bsel(py); B = g_T; C = bsel(py2); }
    else                { A = g_T; B = bsel(pz); C = bsel(pz2); }
    __shared__ float As[32][33], Bs[32][33];
    int tid = threadIdx.x, tx = tid&15, ty = tid>>4;
    int j0 = blockIdx.x*32, i0 = blockIdx.y*32;
    float a00=0,a01=0,a10=0,a11=0;
    for (int k0=0;k0<DIM;k0+=32){
        #pragma unroll
        for (int p=0;p<4;p++){
            int lin = tid+p*256, r = lin>>5, c = lin&31;
            As[r][c] = A[(i0+r)*DIM + k0+c];
            Bs[r][c] = B[(k0+r)*DIM + j0+c];
        }
        __syncthreads();
        #pragma unroll
        for (int kk=0;kk<32;kk++){
            float x0=As[ty*2][kk], x1=As[ty*2+1][kk];
            float y0=Bs[kk][tx*2], y1=Bs[kk][tx*2+1];
            a00=fmaf(x0,y0,a00); a01=fmaf(x0,y1,a01);
            a10=fmaf(x1,y0,a10); a11=fmaf(x1,y1,a11);
        }
        __syncthreads();
    }
    int i = i0+ty*2, j = j0+tx*2;
    C[i*DIM + j]       = a00;
    C[i*DIM + j+1]     = a01;
    C[(i+1)*DIM + j]   = a10;
    C[(i+1)*DIM + j+1] = a11;
}

// merged whiten (support rows y<128, query rows y>=128); f32x2 core
extern "C" __global__ __launch_bounds__(256) void k_whiten(
        const float* __restrict__ sfp, const float* __restrict__ qfp, int zid){
    const float* M = bsel(zid);
    int wsel = (blockIdx.y >= NSUP/128);
    const float* Xin = wsel ? qfp : sfp;
    __nv_bfloat16* Bout = wsel ? g_qhi : g_shi;
    float* Nout = wsel ? g_qn : g_sn;
    int m0 = (wsel ? (int)blockIdx.y - NSUP/128 : (int)blockIdx.y)*128;
    __shared__ float Xs[16][132], Ms[16][68];
    __shared__ float muzp[4][64];
    __shared__ float muz[64];
    int tid = threadIdx.x, tx = tid&15, ty = tid>>4;
    int j0 = blockIdx.x*64;
    { int col = tid>>2, part = tid&3;
      float s = 0.f;
      #pragma unroll 16
      for (int k=part*64; k<part*64+64; k++) s = fmaf(g_mu[k], M[k*DIM + j0 + col], s);
      muzp[part][col] = s; }
    __syncthreads();
    if (tid < 64) muz[tid] = muzp[0][tid]+muzp[1][tid]+muzp[2][tid]+muzp[3][tid];
    unsigned long long acc2[8][2];
    #pragma unroll
    for (int u=0;u<8;u++){ acc2[u][0]=0ull; acc2[u][1]=0ull; }
    for (int k0=0;k0<DIM;k0+=16){
        #pragma unroll
        for (int p=0;p<2;p++){
            int lin = tid+p*256, m = lin>>2, c4 = (lin&3)*4;
            float4 v = *(const float4*)(Xin + (size_t)(m0+m)*DIM + k0 + c4);
            Xs[c4][m]=v.x; Xs[c4+1][m]=v.y; Xs[c4+2][m]=v.z; Xs[c4+3][m]=v.w;
        }
        { int r = tid>>4, c4 = (tid&15)*4;
          *(float4*)&Ms[r][c4] = *(const float4*)(M + (k0+r)*DIM + j0 + c4); }
        __syncthreads();
        #pragma unroll
        for (int kk=0;kk<16;kk++){
            float4 a0 = *(const float4*)&Xs[kk][ty*8];
            float4 a1 = *(const float4*)&Xs[kk][ty*8+4];
            ulonglong2 b = *(const ulonglong2*)&Ms[kk][tx*4];
            unsigned long long ad[8] = {dup2(a0.x), dup2(a0.y), dup2(a0.z), dup2(a0.w),
                                        dup2(a1.x), dup2(a1.y), dup2(a1.z), dup2(a1.w)};
            #pragma unroll
            for (int u=0;u<8;u++){
                ffma2(acc2[u][0], ad[u], b.x);
                ffma2(acc2[u][1], ad[u], b.y);
            }
        }
        __syncthreads();
    }
    float rs = sqrtf((float)DIM / g_trsum);
    float mz[4];
    #pragma unroll
    for (int v=0;v<4;v++) mz[v] = muz[tx*4+v];
    #pragma unroll
    for (int u=0;u<8;u++){
        float2 p0 = unpk(acc2[u][0]), p1 = unpk(acc2[u][1]);
        float av[4] = {p0.x, p0.y, p1.x, p1.y};
        float vv[4]; float ss = 0.f;
        #pragma unroll
        for (int v=0;v<4;v++){ vv[v]=(av[v]-mz[v])*rs; ss += vv[v]*vv[v]; }
        __nv_bfloat16 h[4];
        #pragma unroll
        for (int v=0;v<4;v++) h[v] = __float2bfloat16_rn(vv[v]);
        int row = m0 + ty*8 + u;
        *(ushort4*)(Bout + (size_t)row*DIM + j0 + tx*4) =
            make_ushort4(*(unsigned short*)&h[0], *(unsigned short*)&h[1],
                         *(unsigned short*)&h[2], *(unsigned short*)&h[3]);
        atomicAdd(&Nout[row], ss);
    }
}

// ---- sample d2 GEMM for gamma ---------------------------------------------
#define SMA   0
#define SMB   16384
#define SMX_S 32768
#define SMT_S 40960
#define SMX_M 65536
#define SMT_M 67072

extern "C" __global__ __launch_bounds__(256) void k_d2samp(){
    extern __shared__ char smem[];
    uint32_t sb = smem_u32(smem);
    unsigned int* sh = (unsigned int*)(smem + SMX_S);
    int tid = threadIdx.x, wid = tid>>5, lane = tid&31;
    int m0 = blockIdx.y*128, n0 = blockIdx.x*128;
    int wm0 = (wid&1)*64, wn0 = (wid>>1)*32;
    for (int b=tid;b<SBIN;b+=256) sh[b]=0u;
    float acc[4][4][4] = {};
    int g = lane>>3, lr = lane&7;
    for (int kc=0;kc<4;kc++){
        #pragma unroll
        for (int p=0;p<4;p++){
            int idx = tid + p*256;
            int r = idx>>3, c = idx&7;
            size_t go = (size_t)r*DIM + kc*64 + c*8;
            uint32_t so = (uint32_t)(r*128 + ((c ^ (r&7))<<4));
            *(uint4*)(smem+SMA+so) = *(const uint4*)(g_qhi + (size_t)m0*DIM + go);
            *(uint4*)(smem+SMB+so) = *(const uint4*)(g_shi + (size_t)n0*DIM + go);
        }
        __syncthreads();
        #pragma unroll
        for (int s=0;s<4;s++){
            int cc = s*2 + (g>>1);
            uint32_t a[4][4], bfr[4][2];
            #pragma unroll
            for (int mf=0;mf<4;mf++){
                int r = wm0 + mf*16 + (g&1)*8 + lr;
                LDSM4(a[mf][0],a[mf][1],a[mf][2],a[mf][3], sb + SMA + r*128 + ((cc ^ (r&7))<<4));
            }
            #pragma unroll
            for (int np=0;np<2;np++){
                int r = wn0 + np*16 + (g&1)*8 + lr;
                uint32_t t0,t1,t2,t3;
                LDSM4(t0,t1,t2,t3, sb + SMB + r*128 + ((cc ^ (r&7))<<4));
                bfr[np*2][0]=t0;   bfr[np*2][1]=t2;
                bfr[np*2+1][0]=t1; bfr[np*2+1][1]=t3;
            }
            #pragma unroll
            for (int mf=0;mf<4;mf++)
                #pragma unroll
                for (int nf=0;nf<4;nf++)
                    MMA16816(acc[mf][nf], a[mf], bfr[nf]);
        }
        __syncthreads();
    }
    int rbase = m0 + wm0 + (lane>>2);
    int cbase = n0 + wn0 + (lane&3)*2;
    #pragma unroll
    for (int mf=0;mf<4;mf++)
        #pragma unroll
        for (int h=0;h<2;h++){
            float qn = g_qn[rbase + mf*16 + h*8];
            #pragma unroll
            for (int nf=0;nf<4;nf++){
                int col = cbase + nf*8;
                float v0 = fmaxf(qn + g_sn[col]   - 2.f*acc[mf][nf][h*2+0], 0.f);
                float v1 = fmaxf(qn + g_sn[col+1] - 2.f*acc[mf][nf][h*2+1], 0.f);
                int b0=(int)(v0*2.0f); if(b0>SBIN-1)b0=SBIN-1;
                int b1=(int)(v1*2.0f); if(b1>SBIN-1)b1=SBIN-1;
                atomicAdd(&sh[b0],1u); atomicAdd(&sh[b1],1u);
            }
        }
    __syncthreads();
    for (int b=tid;b<SBIN;b+=256)
        if (sh[b]) atomicAdd(&g_h1[b], sh[b]);
}

extern "C" __global__ void k_gamma(){
    __shared__ unsigned long long ps[256];
    int tid = threadIdx.x;
    unsigned int loc[8];
    unsigned long long s = 0ull;
    #pragma unroll
    for (int t=0;t<8;t++){ loc[t] = g_h1[tid*8+t]; s += loc[t]; }
    ps[tid] = s; __syncthreads();
    for (int o=1;o<256;o<<=1){
        unsigned long long v = (tid>=o) ? ps[tid-o] : 0ull;
        __syncthreads();
        ps[tid] += v;
        __syncthreads();
    }
    unsigned long long before = ps[tid] - s;
    if (before < SKRANK && ps[tid] >= SKRANK){
        unsigned long long cum = before;
        #pragma unroll
        for (int t=0;t<8;t++){
            if (cum + loc[t] >= SKRANK){
                float frac = (float)(SKRANK - cum) / (float)(loc[t] ? loc[t] : 1u);
                float med = ((float)(tid*8+t) + frac) * 0.5f;
                g_gamma = 1.f/(med + 1e-6f);
                break;
            }
            cum += loc[t];
        }
    }
}

// ---- main d2 GEMM: cp.async double-buffered, fused softmax reduction -------
__device__ __forceinline__ void d2_issue_loads(uint32_t sbuf, int m0, int n0,
                                               int kc, int tid){
    #pragma unroll
    for (int p=0;p<4;p++){
        int idx = tid + p*256;
        int r = idx>>3, c = idx&7;
        size_t go = (size_t)r*DIM + kc*64 + c*8;
        uint32_t so = (uint32_t)(r*128 + ((c ^ (r&7))<<4));
        cp16(sbuf + so,         g_qhi + (size_t)m0*DIM + go);
        cp16(sbuf + 16384 + so, g_shi + (size_t)n0*DIM + go);
    }
}

extern "C" __global__ __launch_bounds__(256) void k_d2mma(const float* __restrict__ sv){
    extern __shared__ char smem[];
    uint32_t sb = smem_u32(smem);
    float* rAccW = (float*)(smem + SMX_M);
    float* rAccV = rAccW + 128;
    float* sv_s  = rAccV + 128;
    int tid = threadIdx.x, wid = tid>>5, lane = tid&31;
    int m0 = blockIdx.y*128, n0 = blockIdx.x*128;
    int wm0 = (wid&1)*64, wn0 = (wid>>1)*32;
    ((float*)(smem+SMX_M))[tid] = 0.f;
    if (tid < 128) sv_s[tid] = sv[n0 + tid];
    float acc[4][4][4] = {};
    int g = lane>>3, lr = lane&7;

    d2_issue_loads(sb, m0, n0, 0, tid);
    CP_COMMIT();
    for (int kc=0;kc<4;kc++){
        uint32_t buf = sb + (uint32_t)((kc&1)*32768);
        if (kc < 3){
            d2_issue_loads(sb + (uint32_t)(((kc+1)&1)*32768), m0, n0, kc+1, tid);
            CP_COMMIT();
            CP_WAIT(1);
        } else {
            CP_WAIT(0);
        }
        __syncthreads();
        #pragma unroll
        for (int s=0;s<4;s++){
            int cc = s*2 + (g>>1);
            uint32_t a[4][4], bfr[4][2];
            #pragma unroll
            for (int mf=0;mf<4;mf++){
                int r = wm0 + mf*16 + (g&1)*8 + lr;
                LDSM4(a[mf][0],a[mf][1],a[mf][2],a[mf][3], buf + r*128 + ((cc ^ (r&7))<<4));
            }
            #pragma unroll
            for (int np=0;np<2;np++){
                int r = wn0 + np*16 + (g&1)*8 + lr;
                uint32_t t0,t1,t2,t3;
                LDSM4(t0,t1,t2,t3, buf + 16384 + r*128 + ((cc ^ (r&7))<<4));
                bfr[np*2][0]=t0;   bfr[np*2][1]=t2;
                bfr[np*2+1][0]=t1; bfr[np*2+1][1]=t3;
            }
            #pragma unroll
            for (int mf=0;mf<4;mf++)
                #pragma unroll
                for (int nf=0;nf<4;nf++)
                    MMA16816(acc[mf][nf], a[mf], bfr[nf]);
        }
        __syncthreads();
    }
    float gamma = g_gamma;
    int lr0 = wm0 + (lane>>2);
    int cb = wn0 + (lane&3)*2;
    #pragma unroll
    for (int mf=0;mf<4;mf++)
        #pragma unroll
        for (int h=0;h<2;h++){
            int lrow = lr0 + mf*16 + h*8;
            float qn = g_qn[m0 + lrow];
            float sw = 0.f, swv = 0.f;
            #pragma unroll
            for (int nf=0;nf<4;nf++){
                int col = cb + nf*8;
                float d0 = fmaxf(qn + g_sn[n0+col]   - 2.f*acc[mf][nf][h*2+0], 0.f);
                float d1 = fmaxf(qn + g_sn[n0+col+1] - 2.f*acc[mf][nf][h*2+1], 0.f);
                float w0 = __expf(-gamma*d0);
                float w1 = __expf(-gamma*d1);
                sw  += w0 + w1;
                swv += w0*sv_s[col] + w1*sv_s[col+1];
            }
            sw  += __shfl_xor_sync(0xffffffffu, sw, 1);
            swv += __shfl_xor_sync(0xffffffffu, swv, 1);
            sw  += __shfl_xor_sync(0xffffffffu, sw, 2);
            swv += __shfl_xor_sync(0xffffffffu, swv, 2);
            if ((lane&3)==0){
                atomicAdd(&rAccW[lrow], sw);
                atomicAdd(&rAccV[lrow], swv);
            }
        }
    __syncthreads();
    if (tid < 128){
        atomicAdd(&g_accw[m0+tid],  rAccW[tid]);
        atomicAdd(&g_accwv[m0+tid], rAccV[tid]);
    }
}

extern "C" __global__ void k_predfin(float* __restrict__ out){
    int q = blockIdx.x*blockDim.x + threadIdx.x;
    if (q < NQ) out[(size_t)NQ*NCLS + q] = g_accwv[q]/g_accw[q];
}

extern "C" void kernel_launch(void* const* d_in, const int* in_sizes, int n_in,
                              void* d_out, int out_size){
    const float* sf  = (const float*)d_in[0];
    const int*   lab = (const int*)  d_in[1];
    const float* sv  = (const float*)d_in[2];
    const float* qf  = (const float*)d_in[3];
    float* out = (float*)d_out;
    (void)in_sizes; (void)n_in; (void)out_size;

    cudaFuncSetAttribute(k_d2samp, cudaFuncAttributeMaxDynamicSharedMemorySize, SMT_S);
    cudaFuncSetAttribute(k_d2mma,  cudaFuncAttributeMaxDynamicSharedMemorySize, SMT_M);

    // side stream for independent branches (graph fork/join via events)
    cudaStream_t s2;
    cudaStreamCreate(&s2);
    cudaEvent_t eFork, eCov, eLog;
    cudaEventCreateWithFlags(&eFork, cudaEventDisableTiming);
    cudaEventCreateWithFlags(&eCov,  cudaEventDisableTiming);
    cudaEventCreateWithFlags(&eLog,  cudaEventDisableTiming);

    k_zero<<<256,256>>>();
    cudaEventRecord(eFork, 0);
    cudaStreamWaitEvent(s2, eFork, 0);
    // branch s2: covgemm (independent of support/finalize)
    k_covgemm<<<dim3(10,1,32),256,0,s2>>>(sf);
    cudaEventRecord(eCov, s2);
    // main: support -> finalize
    k_support<<<128,256>>>(sf, lab);
    k_finalize<<<9,256>>>();
    // branch s2: logits (needs finalize only; nothing downstream needs it)
    cudaEventRecord(eFork, 0);
    cudaStreamWaitEvent(s2, eFork, 0);
    k_logits<<<NQ/4,256,0,s2>>>(qf, out);
    cudaEventRecord(eLog, s2);
    // main: needs covgemm done before covA
    cudaStreamWaitEvent(0, eCov, 0);
    k_covA<<<64,256>>>();
    k_covB<<<64,256>>>();
    // NS iter 1 (algebraic): Y0 slot0, T0==Z1 slot1.  Y1 = Y0 @ T0 -> slot3
    k_mm256<<<dim3(8,8),256>>>(0, 1, 3, 1);
    int py=3, pz=1, py2=0, pz2=4;
    for (int it=0; it<2; it++){
        k_mm256<<<dim3(8,8),256>>>(pz, py, 2, 0);
        k_mm256pair<<<dim3(8,8,2),256>>>(py, pz, py2, pz2);
        int t = py; py = py2; py2 = t;
        t = pz; pz = pz2; pz2 = t;
    }
    k_whiten<<<dim3(4, NSUP/128 + NQ/128),256>>>(sf, qf, pz);
    k_d2samp<<<dim3(16,8),256,SMT_S>>>();
    k_gamma<<<1,256>>>();
    k_d2mma<<<dim3(NSUP/128,NQ/128),256,SMT_M>>>(sv);
    // join logits branch back before capture ends
    cudaStreamWaitEvent(0, eLog, 0);
    k_predfin<<<NQ/256,256>>>(out);
}